// round 11
// baseline (speedup 1.0000x reference)
#include <cuda_runtime.h>
#include <cuda_fp16.h>
#include <math.h>
#include <stdint.h>

// Problem constants
constexpr int B_  = 16;
constexpr int L_  = 4096;
constexpr int DI  = 256;   // D_INNER
constexpr int DS  = 16;    // D_STATE
constexpr long BLD = (long)B_ * L_;   // 65536 tokens

constexpr int CL  = 64;          // chunk length for scan
constexpr int NC  = L_ / CL;     // 64 chunks

// ---------------- scratch (device globals; no allocation) ----------------
__device__ float  g_xz  [BLD * 512];      // after W_in (xc_raw | z)
__device__ float  g_xc  [BLD * DI];       // after conv+silu
__device__ float  g_hloc[(long)B_ * NC * DI * DS];
__device__ float  g_hin [(long)B_ * NC * DI * DS];
__device__ float  g_sumdt[(long)B_ * NC * DI];
// fp16 hi/lo activation carries
__device__ __half g_h_hi [BLD * 128];
__device__ __half g_h_lo [BLD * 128];
__device__ __half g_yf_hi[BLD * 256];
__device__ __half g_yf_lo[BLD * 256];
__device__ __half g_t1_hi[BLD * 128];
__device__ __half g_t1_lo[BLD * 128];
// fp16 hi/lo weights
__device__ __half g_wmix_hi[512 * 128], g_wmix_lo[512 * 128];
__device__ __half g_win_hi [128 * 512], g_win_lo [128 * 512];
__device__ __half g_wop_hi [256 * 128], g_wop_lo [256 * 128];
__device__ __half g_wout_hi[128 * 256], g_wout_lo[128 * 256];

// ======================= helpers =========================================
__device__ __forceinline__ uint32_t smem_u32(const void* p) {
    uint32_t a;
    asm("{ .reg .u64 t; cvta.to.shared.u64 t, %1; cvt.u32.u64 %0, t; }"
        : "=r"(a) : "l"(p));
    return a;
}
__device__ __forceinline__ void cpa16(uint32_t dst, const void* src) {
    asm volatile("cp.async.cg.shared.global [%0], [%1], 16;"
                 :: "r"(dst), "l"(src) : "memory");
}
__device__ __forceinline__ void cpa_commit() {
    asm volatile("cp.async.commit_group;" ::: "memory");
}
__device__ __forceinline__ void cpa_wait0() {
    asm volatile("cp.async.wait_group 0;" ::: "memory");
}
__device__ __forceinline__ void ldsm_x4(uint32_t* r, uint32_t addr) {
    asm volatile("ldmatrix.sync.aligned.m8n8.x4.shared.b16 {%0,%1,%2,%3}, [%4];"
        : "=r"(r[0]), "=r"(r[1]), "=r"(r[2]), "=r"(r[3]) : "r"(addr));
}
__device__ __forceinline__ void ldsm_x4_t(uint32_t* r, uint32_t addr) {
    asm volatile("ldmatrix.sync.aligned.m8n8.x4.trans.shared.b16 {%0,%1,%2,%3}, [%4];"
        : "=r"(r[0]), "=r"(r[1]), "=r"(r[2]), "=r"(r[3]) : "r"(addr));
}
__device__ __forceinline__ void mma16816(float* c, const uint32_t* a,
                                         uint32_t b0, uint32_t b1) {
    asm volatile("mma.sync.aligned.m16n8k16.row.col.f32.f16.f16.f32 "
        "{%0,%1,%2,%3}, {%4,%5,%6,%7}, {%8,%9}, {%0,%1,%2,%3};"
        : "+f"(c[0]), "+f"(c[1]), "+f"(c[2]), "+f"(c[3])
        : "r"(a[0]), "r"(a[1]), "r"(a[2]), "r"(a[3]), "r"(b0), "r"(b1));
}

// ---------------- fused weight splitter (all 4 weights, one launch) -------
__global__ void split_all(const float* __restrict__ Wmix,
                          const float* __restrict__ Win,
                          const float* __restrict__ Wop,
                          const float* __restrict__ Wout,
                          __half* __restrict__ mh, __half* __restrict__ ml,
                          __half* __restrict__ ih, __half* __restrict__ il,
                          __half* __restrict__ oh, __half* __restrict__ ol,
                          __half* __restrict__ uh, __half* __restrict__ ul)
{
    int i = blockIdx.x * 256 + threadIdx.x;   // 0..196607
    const float* src; __half *dh, *dl; int j;
    if (i < 65536)        { src = Wmix; dh = mh; dl = ml; j = i; }
    else if (i < 131072)  { src = Win;  dh = ih; dl = il; j = i - 65536; }
    else if (i < 163840)  { src = Wop;  dh = oh; dl = ol; j = i - 131072; }
    else                  { src = Wout; dh = uh; dl = ul; j = i - 163840; }
    float v = src[j];
    __half h = __float2half_rn(v);
    dh[j] = h;
    dl[j] = __float2half_rn(v - __half2float(h));
}

// ====== tensor-core GEMM (mma.sync, fp16 hi/lo, compact smem) ============
constexpr int SAW2 = 72;
constexpr int SBW  = 136;
constexpr int SMEM_A2 = 128 * SAW2 * 2;    // 18432
constexpr int SMEM_B2 = 64 * SBW * 2;      // 17408
constexpr int SM_STAGE2 = SMEM_A2 + SMEM_B2;   // 35840
constexpr int GEMM_SMEM2 = 2 * SM_STAGE2;      // 71680

template<bool ASPLIT, bool OSPLIT>
__global__ __launch_bounds__(256) void tcgemm2(
    const float* __restrict__ A0f, const float* __restrict__ A1f,
    int K0, int sA0, int sA1,
    const __half* __restrict__ Ahi, const __half* __restrict__ Alo,
    const __half* __restrict__ Whi, const __half* __restrict__ Wlo,
    const float* __restrict__ bias,
    float* __restrict__ Cf, __half* __restrict__ Chi, __half* __restrict__ Clo,
    int N, int K)
{
    extern __shared__ char smem[];
    const int tid = threadIdx.x;
    const int wid = tid >> 5, lane = tid & 31;
    const int wm = wid & 3, wn = wid >> 2;
    const long rowBase = (long)blockIdx.y * 128;
    const int  colBase = blockIdx.x * 128;

    float acc[2][8][4];
#pragma unroll
    for (int i = 0; i < 2; i++)
#pragma unroll
        for (int j = 0; j < 8; j++)
#pragma unroll
            for (int e = 0; e < 4; e++) acc[i][j][e] = 0.f;

    const uint32_t sb0 = smem_u32(smem);
    uint32_t aAddr[2], bAddr[4];
#pragma unroll
    for (int mf = 0; mf < 2; mf++)
        aAddr[mf] = sb0 + (uint32_t)(((wm * 32 + mf * 16 + (lane & 15)) * SAW2
                                      + (lane >> 4) * 8) * 2);
#pragma unroll
    for (int ng = 0; ng < 4; ng++)
        bAddr[ng] = sb0 + SMEM_A2 + (uint32_t)(((lane & 15) * SBW
                                      + wn * 64 + ng * 16 + (lane >> 4) * 8) * 2);

    const int nch = K / 32;

    auto loadTiles = [&](int ch, int st) {
        const int kt = ch * 32;
        const uint32_t sbA = sb0 + st * SM_STAGE2;
        const uint32_t sbB = sbA + SMEM_A2;
#pragma unroll
        for (int i = 0; i < 4; i++) {
            int lin = tid + i * 256;
            int row = lin >> 4, u = lin & 15;
            const __half* src = ((row >= 32) ? Wlo : Whi)
                + (long)(kt + (row & 31)) * N + colBase + u * 8;
            cpa16(sbB + (uint32_t)(row * SBW + u * 8) * 2, src);
        }
        if (ASPLIT) {
            const int r = tid >> 1, q = tid & 1;
            const __half* sh = Ahi + (rowBase + r) * (long)K + kt + q * 16;
            const __half* sl = Alo + (rowBase + r) * (long)K + kt + q * 16;
            uint32_t dh = sbA + (uint32_t)(r * SAW2 + q * 16) * 2;
            uint32_t dl = sbA + (uint32_t)(r * SAW2 + 32 + q * 16) * 2;
            cpa16(dh, sh);      cpa16(dh + 16, sh + 8);
            cpa16(dl, sl);      cpa16(dl + 16, sl + 8);
        } else {
            const float* Ap; int sA_, kof;
            if (kt < K0) { Ap = A0f; sA_ = sA0; kof = kt; }
            else         { Ap = A1f; sA_ = sA1; kof = kt - K0; }
            const int r = tid >> 1, q = tid & 1;
            const float4* src = reinterpret_cast<const float4*>(
                Ap + (rowBase + r) * (long)sA_ + kof + q * 16);
            __half* rowp = reinterpret_cast<__half*>(smem + st * SM_STAGE2)
                           + r * SAW2;
#pragma unroll
            for (int j = 0; j < 4; j++) {
                float4 v = src[j];
                int c = q * 16 + j * 4;
                __half hx = __float2half_rn(v.x), hy = __float2half_rn(v.y);
                __half hz = __float2half_rn(v.z), hw = __float2half_rn(v.w);
                __half lx = __float2half_rn(v.x - __half2float(hx));
                __half ly = __float2half_rn(v.y - __half2float(hy));
                __half lz = __float2half_rn(v.z - __half2float(hz));
                __half lw = __float2half_rn(v.w - __half2float(hw));
                __half2 h01 = __halves2half2(hx, hy), h23 = __halves2half2(hz, hw);
                __half2 l01 = __halves2half2(lx, ly), l23 = __halves2half2(lz, lw);
                *reinterpret_cast<uint2*>(rowp + c) =
                    make_uint2(*(uint32_t*)&h01, *(uint32_t*)&h23);
                *reinterpret_cast<uint2*>(rowp + 32 + c) =
                    make_uint2(*(uint32_t*)&l01, *(uint32_t*)&l23);
            }
        }
    };

    loadTiles(0, 0);
    cpa_commit();

    for (int ch = 0; ch < nch; ch++) {
        cpa_wait0();
        __syncthreads();
        if (ch + 1 < nch) { loadTiles(ch + 1, (ch + 1) & 1); cpa_commit(); }

        const uint32_t so = (uint32_t)((ch & 1) * SM_STAGE2);
        const int aof[6] = {0, 16, 32, 48, 0, 16};
        const int bof[6] = {0, 16, 0, 16, 32, 48};
#pragma unroll
        for (int s = 0; s < 6; s++) {
            uint32_t afr[2][4];
            ldsm_x4(afr[0], aAddr[0] + so + aof[s] * 2);
            ldsm_x4(afr[1], aAddr[1] + so + aof[s] * 2);
            uint32_t bfr[4][4];
#pragma unroll
            for (int ng = 0; ng < 4; ng++)
                ldsm_x4_t(bfr[ng], bAddr[ng] + so + bof[s] * SBW * 2);
#pragma unroll
            for (int ng = 0; ng < 4; ng++) {
#pragma unroll
                for (int mf = 0; mf < 2; mf++) {
                    mma16816(acc[mf][ng * 2],     afr[mf], bfr[ng][0], bfr[ng][1]);
                    mma16816(acc[mf][ng * 2 + 1], afr[mf], bfr[ng][2], bfr[ng][3]);
                }
            }
        }
    }

    // ---- epilogue ----
#pragma unroll
    for (int mf = 0; mf < 2; mf++) {
        long row = rowBase + wm * 32 + mf * 16 + (lane >> 2);
#pragma unroll
        for (int nf = 0; nf < 8; nf++) {
            int col = colBase + wn * 64 + nf * 8 + (lane & 3) * 2;
            float bx = bias[col], by = bias[col + 1];
            float v0 = acc[mf][nf][0] + bx, v1 = acc[mf][nf][1] + by;
            float v2 = acc[mf][nf][2] + bx, v3 = acc[mf][nf][3] + by;
            if (OSPLIT) {
                __half h0 = __float2half_rn(v0), h1 = __float2half_rn(v1);
                __half h2 = __float2half_rn(v2), h3 = __float2half_rn(v3);
                __half2 hi0 = __halves2half2(h0, h1), hi1 = __halves2half2(h2, h3);
                __half2 lo0 = __halves2half2(
                    __float2half_rn(v0 - __half2float(h0)),
                    __float2half_rn(v1 - __half2float(h1)));
                __half2 lo1 = __halves2half2(
                    __float2half_rn(v2 - __half2float(h2)),
                    __float2half_rn(v3 - __half2float(h3)));
                *reinterpret_cast<__half2*>(Chi + row * (long)N + col) = hi0;
                *reinterpret_cast<__half2*>(Clo + row * (long)N + col) = lo0;
                *reinterpret_cast<__half2*>(Chi + (row + 8) * (long)N + col) = hi1;
                *reinterpret_cast<__half2*>(Clo + (row + 8) * (long)N + col) = lo1;
            } else {
                *reinterpret_cast<float2*>(Cf + row * (long)N + col) =
                    make_float2(v0, v1);
                *reinterpret_cast<float2*>(Cf + (row + 8) * (long)N + col) =
                    make_float2(v2, v3);
            }
        }
    }
}

// ---------------- depthwise causal conv + SiLU, rolling window ------------
// thread = (16-token chunk, d). 16 | L so chunks never cross sequences.
__global__ void conv_silu_kernel(const float* __restrict__ xz,
                                 const float* __restrict__ cw,
                                 const float* __restrict__ cb,
                                 float* __restrict__ xc)
{
    int gid = blockIdx.x * 256 + threadIdx.x;   // 0 .. 1048575
    int d = gid & 255;
    long tb = (long)(gid >> 8) * 16;            // token base
    int l = (int)(tb & (L_ - 1));

    const float w0 = cw[d * 4 + 0], w1 = cw[d * 4 + 1];
    const float w2 = cw[d * 4 + 2], w3 = cw[d * 4 + 3];
    const float cbd = cb[d];

    float x3 = 0.f, x2 = 0.f, x1 = 0.f;
    if (l > 0) {            // l is a multiple of 16, so l >= 16 > 3 here
        x3 = xz[(tb - 3) * 512 + d];
        x2 = xz[(tb - 2) * 512 + d];
        x1 = xz[(tb - 1) * 512 + d];
    }
#pragma unroll
    for (int t = 0; t < 16; t++) {
        float xt = xz[(tb + t) * 512 + d];
        float a = cbd + w0 * x3 + w1 * x2 + w2 * x1 + w3 * xt;
        float s = 1.f / (1.f + __expf(-a));
        xc[(tb + t) * 256 + d] = a * s;
        x3 = x2; x2 = x1; x1 = xt;
    }
}

// ====== scan kernels with fused xproj + dt recompute =====================
// smem: xcs[64][260] (float4-aligned pad; bank = (4t+k)%32, conflict-free
// for a warp's 8-t span) | Wxs[256*40] overlaid by dbls[64][40] after use.
constexpr int XCW = 260;
constexpr int SCAN_SMEM = (64 * XCW + 256 * 40) * 4;   // 107520 B

__global__ __launch_bounds__(256) void scanA_kernel(
    const float* __restrict__ xcg, const float* __restrict__ Wx,
    const float* __restrict__ W_dt, const float* __restrict__ b_dt,
    const float* __restrict__ A_log,
    float* __restrict__ hloc, float* __restrict__ sumdtArr)
{
    extern __shared__ float fs[];
    float* xcs  = fs;                 // [64][XCW]
    float* Wxs  = fs + 64 * XCW;      // [256*40] (phase 1-2)
    float* dbls = fs + 64 * XCW;      // [64][40] (overlays Wxs, phase 3)

    const int bid = blockIdx.x;
    const int b = bid / NC, c = bid % NC;
    const long mbase = (long)b * L_ + (long)c * CL;
    const int d = threadIdx.x;

    float Ar[16]; bool fast = true;
#pragma unroll
    for (int s = 0; s < 16; s++) {
        Ar[s] = -__expf(A_log[d * 16 + s]);
        float n = (float)(s + 1);
        fast = fast && (fabsf(Ar[s] + n) < 1e-3f * n);
    }
    float wdt[8];
#pragma unroll
    for (int k = 0; k < 8; k++) wdt[k] = W_dt[k * 256 + d];
    const float bb = b_dt[d];

    // load xc tile [64][256] -> xcs, and Wx -> Wxs
#pragma unroll
    for (int it = 0; it < 16; it++) {
        int idx = d + it * 256;        // float4 units, 0..4095
        int row = idx >> 6, q = idx & 63;
        float4 v = *reinterpret_cast<const float4*>(
            xcg + (mbase + row) * 256 + q * 4);
        *reinterpret_cast<float4*>(&xcs[row * XCW + q * 4]) = v;
    }
#pragma unroll
    for (int it = 0; it < 10; it++) {
        int idx = d + it * 256;        // 0..2559
        reinterpret_cast<float4*>(Wxs)[idx] =
            reinterpret_cast<const float4*>(Wx)[idx];
    }
    __syncthreads();

    // fused xproj: thread (t = d>>2, jg = d&3) -> dbl[t][jg*10 .. +10)
    float pacc[10];
#pragma unroll
    for (int j = 0; j < 10; j++) pacc[j] = 0.f;
    {
        const int t = d >> 2, jg = d & 3;
        const float* xrow = xcs + t * XCW;
        const float* wbase = Wxs + jg * 10;
        for (int k = 0; k < 256; k++) {
            float xv = xrow[k];
            const float* w = wbase + k * 40;
#pragma unroll
            for (int jj = 0; jj < 10; jj++) pacc[jj] += xv * w[jj];
        }
    }
    __syncthreads();
    {
        const int t = d >> 2, jg = d & 3;
#pragma unroll
        for (int jj = 0; jj < 10; jj++) dbls[t * 40 + jg * 10 + jj] = pacc[jj];
    }
    __syncthreads();

    // scan
    float h[16];
#pragma unroll
    for (int s = 0; s < 16; s++) h[s] = 0.f;
    float sumdt = 0.f;

    for (int t = 0; t < CL; t++) {
        float pre = bb;
#pragma unroll
        for (int k = 0; k < 8; k++) pre += dbls[t * 40 + k] * wdt[k];
        float e = __expf(pre);
        float dtv = (pre > 15.f) ? pre : __logf(1.f + e);
        float p = __fdividef(1.f, 1.f + e);       // exp(-softplus(pre))
        float xv = xcs[t * XCW + d];
        sumdt += dtv;
        float cc = dtv * xv;
        float pw[16];
        if (fast) {
            float p2 = p * p, p4 = p2 * p2, p8 = p4 * p4;
            pw[0] = p;        pw[1] = p2;       pw[2] = p2 * p;    pw[3] = p4;
            pw[4] = p4 * p;   pw[5] = p4 * p2;  pw[6] = p4 * pw[2];
            pw[7] = p8;       pw[8] = p8 * p;   pw[9] = p8 * p2;   pw[10] = p8 * pw[2];
            pw[11] = p8 * p4; pw[12] = p8 * pw[4]; pw[13] = p8 * pw[5];
            pw[14] = p8 * pw[6]; pw[15] = p8 * p8;
        } else {
#pragma unroll
            for (int s = 0; s < 16; s++) pw[s] = __expf(dtv * Ar[s]);
        }
#pragma unroll
        for (int s = 0; s < 16; s++)
            h[s] = pw[s] * h[s] + cc * dbls[t * 40 + 8 + s];
    }

    long o = ((long)bid * 256 + d) * 16;
#pragma unroll
    for (int s = 0; s < 16; s += 4)
        *reinterpret_cast<float4*>(hloc + o + s) =
            make_float4(h[s], h[s + 1], h[s + 2], h[s + 3]);
    sumdtArr[(long)bid * 256 + d] = sumdt;
}

// ---------------- scan phase B ------------------------------------------
__global__ void scanB_kernel(const float* __restrict__ hloc,
                             const float* __restrict__ sumdtArr,
                             const float* __restrict__ A_log,
                             float* __restrict__ hin)
{
    int gid = blockIdx.x * 256 + threadIdx.x;
    int b = gid >> 12;
    int r = gid & 4095;
    int d = r >> 4, s = r & 15;
    float As_ = -__expf(A_log[d * 16 + s]);
    float h = 0.f;
    for (int c = 0; c < NC; c++) {
        long idx = ((long)(b * NC + c) * 256 + d);
        hin[idx * 16 + s] = h;
        float pw = __expf(As_ * sumdtArr[idx]);
        h = pw * h + hloc[idx * 16 + s];
    }
}

// ---------------- scan phase C: fused xproj + replay + gate ---------------
__global__ __launch_bounds__(256) void scanC_kernel(
    const float* __restrict__ xcg, const float* __restrict__ xz,
    const float* __restrict__ Wx,
    const float* __restrict__ W_dt, const float* __restrict__ b_dt,
    const float* __restrict__ A_log, const float* __restrict__ Dp,
    const float* __restrict__ hin,
    __half* __restrict__ yhi, __half* __restrict__ ylo)
{
    extern __shared__ float fs[];
    float* xcs  = fs;
    float* Wxs  = fs + 64 * XCW;
    float* dbls = fs + 64 * XCW;

    const int bid = blockIdx.x;
    const int b = bid / NC, c = bid % NC;
    const long mbase = (long)b * L_ + (long)c * CL;
    const int d = threadIdx.x;

    float Ar[16]; bool fast = true;
#pragma unroll
    for (int s = 0; s < 16; s++) {
        Ar[s] = -__expf(A_log[d * 16 + s]);
        float n = (float)(s + 1);
        fast = fast && (fabsf(Ar[s] + n) < 1e-3f * n);
    }
    float wdt[8];
#pragma unroll
    for (int k = 0; k < 8; k++) wdt[k] = W_dt[k * 256 + d];
    const float bb = b_dt[d];

#pragma unroll
    for (int it = 0; it < 16; it++) {
        int idx = d + it * 256;
        int row = idx >> 6, q = idx & 63;
        float4 v = *reinterpret_cast<const float4*>(
            xcg + (mbase + row) * 256 + q * 4);
        *reinterpret_cast<float4*>(&xcs[row * XCW + q * 4]) = v;
    }
#pragma unroll
    for (int it = 0; it < 10; it++) {
        int idx = d + it * 256;
        reinterpret_cast<float4*>(Wxs)[idx] =
            reinterpret_cast<const float4*>(Wx)[idx];
    }
    __syncthreads();

    float pacc[10];
#pragma unroll
    for (int j = 0; j < 10; j++) pacc[j] = 0.f;
    {
        const int t = d >> 2, jg = d & 3;
        const float* xrow = xcs + t * XCW;
        const float* wbase = Wxs + jg * 10;
        for (int k = 0; k < 256; k++) {
            float xv = xrow[k];
            const float* w = wbase + k * 40;
#pragma unroll
            for (int jj = 0; jj < 10; jj++) pacc[jj] += xv * w[jj];
        }
    }
    __syncthreads();
    {
        const int t = d >> 2, jg = d & 3;
#pragma unroll
        for (int jj = 0; jj < 10; jj++) dbls[t * 40 + jg * 10 + jj] = pacc[jj];
    }
    __syncthreads();

    float h[16];
    long o = ((long)bid * 256 + d) * 16;
#pragma unroll
    for (int s = 0; s < 16; s += 4) {
        float4 v = *reinterpret_cast<const float4*>(hin + o + s);
        h[s] = v.x; h[s + 1] = v.y; h[s + 2] = v.z; h[s + 3] = v.w;
    }
    const float Dd = Dp[d];

    for (int t = 0; t < CL; t++) {
        long m = mbase + t;
        float pre = bb;
#pragma unroll
        for (int k = 0; k < 8; k++) pre += dbls[t * 40 + k] * wdt[k];
        float e = __expf(pre);
        float dtv = (pre > 15.f) ? pre : __logf(1.f + e);
        float p = __fdividef(1.f, 1.f + e);
        float xv = xcs[t * XCW + d];
        float cc = dtv * xv;
        float pw[16];
        if (fast) {
            float p2 = p * p, p4 = p2 * p2, p8 = p4 * p4;
            pw[0] = p;        pw[1] = p2;       pw[2] = p2 * p;    pw[3] = p4;
            pw[4] = p4 * p;   pw[5] = p4 * p2;  pw[6] = p4 * pw[2];
            pw[7] = p8;       pw[8] = p8 * p;   pw[9] = p8 * p2;   pw[10] = p8 * pw[2];
            pw[11] = p8 * p4; pw[12] = p8 * pw[4]; pw[13] = p8 * pw[5];
            pw[14] = p8 * pw[6]; pw[15] = p8 * p8;
        } else {
#pragma unroll
            for (int s = 0; s < 16; s++) pw[s] = __expf(dtv * Ar[s]);
        }
        float y = 0.f;
#pragma unroll
        for (int s = 0; s < 16; s++) {
            h[s] = pw[s] * h[s] + cc * dbls[t * 40 + 8 + s];
            y += h[s] * dbls[t * 40 + 24 + s];
        }
        float zv = xz[m * 512 + 256 + d];
        float sg = 1.f / (1.f + __expf(-zv));
        float v = (y + xv * Dd) * (zv * sg);
        __half hh = __float2half_rn(v);
        yhi[m * 256 + d] = hh;
        ylo[m * 256 + d] = __float2half_rn(v - __half2float(hh));
    }
}

// ---------------- launcher (stateless, call-invariant) --------------------
extern "C" void kernel_launch(void* const* d_in, const int* in_sizes, int n_in,
                              void* d_out, int out_size)
{
    const float* x      = (const float*)d_in[0];
    const float* qk     = (const float*)d_in[1];
    const float* W_mix  = (const float*)d_in[2];
    const float* b_mix  = (const float*)d_in[3];
    const float* W_in   = (const float*)d_in[4];
    const float* b_in   = (const float*)d_in[5];
    const float* conv_w = (const float*)d_in[6];
    const float* conv_b = (const float*)d_in[7];
    const float* W_xproj= (const float*)d_in[8];
    const float* W_dt   = (const float*)d_in[9];
    const float* b_dt   = (const float*)d_in[10];
    const float* A_log  = (const float*)d_in[11];
    const float* D_param= (const float*)d_in[12];
    const float* W_op   = (const float*)d_in[13];
    const float* b_op   = (const float*)d_in[14];
    const float* W_out  = (const float*)d_in[15];
    const float* b_out  = (const float*)d_in[16];
    float* out = (float*)d_out;

    float  *pxz, *pxc, *phloc, *phin, *psum;
    __half *phhi, *phlo, *pyhi, *pylo, *pt1hi, *pt1lo;
    __half *pwmixh, *pwmixl, *pwinh, *pwinl, *pwoph, *pwopl, *pwouth, *pwoutl;
    cudaGetSymbolAddress((void**)&pxz,   g_xz);
    cudaGetSymbolAddress((void**)&pxc,   g_xc);
    cudaGetSymbolAddress((void**)&phloc, g_hloc);
    cudaGetSymbolAddress((void**)&phin,  g_hin);
    cudaGetSymbolAddress((void**)&psum,  g_sumdt);
    cudaGetSymbolAddress((void**)&phhi,  g_h_hi);
    cudaGetSymbolAddress((void**)&phlo,  g_h_lo);
    cudaGetSymbolAddress((void**)&pyhi,  g_yf_hi);
    cudaGetSymbolAddress((void**)&pylo,  g_yf_lo);
    cudaGetSymbolAddress((void**)&pt1hi, g_t1_hi);
    cudaGetSymbolAddress((void**)&pt1lo, g_t1_lo);
    cudaGetSymbolAddress((void**)&pwmixh, g_wmix_hi);
    cudaGetSymbolAddress((void**)&pwmixl, g_wmix_lo);
    cudaGetSymbolAddress((void**)&pwinh,  g_win_hi);
    cudaGetSymbolAddress((void**)&pwinl,  g_win_lo);
    cudaGetSymbolAddress((void**)&pwoph,  g_wop_hi);
    cudaGetSymbolAddress((void**)&pwopl,  g_wop_lo);
    cudaGetSymbolAddress((void**)&pwouth, g_wout_hi);
    cudaGetSymbolAddress((void**)&pwoutl, g_wout_lo);
    cudaFuncSetAttribute(tcgemm2<false, true>,
        cudaFuncAttributeMaxDynamicSharedMemorySize, GEMM_SMEM2);
    cudaFuncSetAttribute(tcgemm2<true, false>,
        cudaFuncAttributeMaxDynamicSharedMemorySize, GEMM_SMEM2);
    cudaFuncSetAttribute(tcgemm2<true, true>,
        cudaFuncAttributeMaxDynamicSharedMemorySize, GEMM_SMEM2);
    cudaFuncSetAttribute(scanA_kernel,
        cudaFuncAttributeMaxDynamicSharedMemorySize, SCAN_SMEM);
    cudaFuncSetAttribute(scanC_kernel,
        cudaFuncAttributeMaxDynamicSharedMemorySize, SCAN_SMEM);

    dim3 blk(256);
    // all four weight splits in one launch (196608 elements)
    split_all<<<768, 256>>>(W_mix, W_in, W_op, W_out,
                            pwmixh, pwmixl, pwinh, pwinl,
                            pwoph, pwopl, pwouth, pwoutl);

    // h = concat(x,qk) @ W_mix + b_mix  -> fp16 hi/lo   [65536,128], K=512
    tcgemm2<false, true><<<dim3(1, 512), blk, GEMM_SMEM2>>>(
        x, qk, 256, 256, 256, nullptr, nullptr,
        pwmixh, pwmixl, b_mix, nullptr, phhi, phlo, 128, 512);
    // xz = h @ W_in + b_in  -> fp32                      [65536,512], K=128
    tcgemm2<true, false><<<dim3(4, 512), blk, GEMM_SMEM2>>>(
        nullptr, nullptr, 0, 0, 0, phhi, phlo,
        pwinh, pwinl, b_in, pxz, nullptr, nullptr, 512, 128);
    // xc = silu(causal_conv(xz[:, :256])) — rolling window
    conv_silu_kernel<<<4096, 256>>>(pxz, conv_w, conv_b, pxc);
    // chunked selective scan (xproj + dt fused into scanA/scanC)
    scanA_kernel<<<B_ * NC, 256, SCAN_SMEM>>>(
        pxc, W_xproj, W_dt, b_dt, A_log, phloc, psum);
    scanB_kernel<<<256, 256>>>(phloc, psum, A_log, phin);
    scanC_kernel<<<B_ * NC, 256, SCAN_SMEM>>>(
        pxc, pxz, W_xproj, W_dt, b_dt, A_log, D_param, phin, pyhi, pylo);
    // t1 = yf @ W_op + b_op  -> fp16 hi/lo                [65536,128], K=256
    tcgemm2<true, true><<<dim3(1, 512), blk, GEMM_SMEM2>>>(
        nullptr, nullptr, 0, 0, 0, pyhi, pylo,
        pwoph, pwopl, b_op, nullptr, pt1hi, pt1lo, 128, 256);
    // out = t1 @ W_out + b_out -> fp32                    [65536,256], K=128
    tcgemm2<true, false><<<dim3(2, 512), blk, GEMM_SMEM2>>>(
        nullptr, nullptr, 0, 0, 0, pt1hi, pt1lo,
        pwouth, pwoutl, b_out, out, nullptr, nullptr, 256, 128);
}

// round 12
// speedup vs baseline: 1.1543x; 1.1543x over previous
#include <cuda_runtime.h>
#include <cuda_fp16.h>
#include <math.h>
#include <stdint.h>

// Problem constants
constexpr int B_  = 16;
constexpr int L_  = 4096;
constexpr int DI  = 256;   // D_INNER
constexpr int DS  = 16;    // D_STATE
constexpr long BLD = (long)B_ * L_;   // 65536 tokens

constexpr int CL  = 64;          // chunk length for scan
constexpr int NC  = L_ / CL;     // 64 chunks

// ---------------- scratch (device globals; no allocation) ----------------
__device__ float  g_xz  [BLD * 512];      // after W_in (xc_raw | z)
__device__ float  g_xc  [BLD * DI];       // after conv+silu
__device__ float  g_dbl [BLD * 40];       // xproj output (dtrank|B|C)
__device__ float  g_hloc[(long)B_ * NC * DI * DS];
__device__ float  g_hin [(long)B_ * NC * DI * DS];
__device__ float  g_sumdt[(long)B_ * NC * DI];
// fp16 hi/lo activation carries
__device__ __half g_h_hi [BLD * 128];
__device__ __half g_h_lo [BLD * 128];
__device__ __half g_yf_hi[BLD * 256];
__device__ __half g_yf_lo[BLD * 256];
__device__ __half g_t1_hi[BLD * 128];
__device__ __half g_t1_lo[BLD * 128];
// fp16 hi/lo weights
__device__ __half g_wmix_hi[512 * 128], g_wmix_lo[512 * 128];
__device__ __half g_win_hi [128 * 512], g_win_lo [128 * 512];
__device__ __half g_wop_hi [256 * 128], g_wop_lo [256 * 128];
__device__ __half g_wout_hi[128 * 256], g_wout_lo[128 * 256];

// ======================= helpers =========================================
__device__ __forceinline__ uint32_t smem_u32(const void* p) {
    uint32_t a;
    asm("{ .reg .u64 t; cvta.to.shared.u64 t, %1; cvt.u32.u64 %0, t; }"
        : "=r"(a) : "l"(p));
    return a;
}
__device__ __forceinline__ void cpa16(uint32_t dst, const void* src) {
    asm volatile("cp.async.cg.shared.global [%0], [%1], 16;"
                 :: "r"(dst), "l"(src) : "memory");
}
__device__ __forceinline__ void cpa_commit() {
    asm volatile("cp.async.commit_group;" ::: "memory");
}
__device__ __forceinline__ void cpa_wait0() {
    asm volatile("cp.async.wait_group 0;" ::: "memory");
}
__device__ __forceinline__ void ldsm_x4(uint32_t* r, uint32_t addr) {
    asm volatile("ldmatrix.sync.aligned.m8n8.x4.shared.b16 {%0,%1,%2,%3}, [%4];"
        : "=r"(r[0]), "=r"(r[1]), "=r"(r[2]), "=r"(r[3]) : "r"(addr));
}
__device__ __forceinline__ void ldsm_x4_t(uint32_t* r, uint32_t addr) {
    asm volatile("ldmatrix.sync.aligned.m8n8.x4.trans.shared.b16 {%0,%1,%2,%3}, [%4];"
        : "=r"(r[0]), "=r"(r[1]), "=r"(r[2]), "=r"(r[3]) : "r"(addr));
}
__device__ __forceinline__ void mma16816(float* c, const uint32_t* a,
                                         uint32_t b0, uint32_t b1) {
    asm volatile("mma.sync.aligned.m16n8k16.row.col.f32.f16.f16.f32 "
        "{%0,%1,%2,%3}, {%4,%5,%6,%7}, {%8,%9}, {%0,%1,%2,%3};"
        : "+f"(c[0]), "+f"(c[1]), "+f"(c[2]), "+f"(c[3])
        : "r"(a[0]), "r"(a[1]), "r"(a[2]), "r"(a[3]), "r"(b0), "r"(b1));
}

// ---------------- fused weight splitter (all 4 weights, one launch) -------
__global__ void split_all(const float* __restrict__ Wmix,
                          const float* __restrict__ Win,
                          const float* __restrict__ Wop,
                          const float* __restrict__ Wout,
                          __half* __restrict__ mh, __half* __restrict__ ml,
                          __half* __restrict__ ih, __half* __restrict__ il,
                          __half* __restrict__ oh, __half* __restrict__ ol,
                          __half* __restrict__ uh, __half* __restrict__ ul)
{
    int i = blockIdx.x * 256 + threadIdx.x;   // 0..196607
    const float* src; __half *dh, *dl; int j;
    if (i < 65536)        { src = Wmix; dh = mh; dl = ml; j = i; }
    else if (i < 131072)  { src = Win;  dh = ih; dl = il; j = i - 65536; }
    else if (i < 163840)  { src = Wop;  dh = oh; dl = ol; j = i - 131072; }
    else                  { src = Wout; dh = uh; dl = ul; j = i - 163840; }
    float v = src[j];
    __half h = __float2half_rn(v);
    dh[j] = h;
    dl[j] = __float2half_rn(v - __half2float(h));
}

// ====== tensor-core GEMM (mma.sync, fp16 hi/lo, compact smem) ============
constexpr int SAW2 = 72;
constexpr int SBW  = 136;
constexpr int SMEM_A2 = 128 * SAW2 * 2;    // 18432
constexpr int SMEM_B2 = 64 * SBW * 2;      // 17408
constexpr int SM_STAGE2 = SMEM_A2 + SMEM_B2;   // 35840
constexpr int GEMM_SMEM2 = 2 * SM_STAGE2;      // 71680

template<bool ASPLIT, bool OSPLIT>
__global__ __launch_bounds__(256) void tcgemm2(
    const float* __restrict__ A0f, const float* __restrict__ A1f,
    int K0, int sA0, int sA1,
    const __half* __restrict__ Ahi, const __half* __restrict__ Alo,
    const __half* __restrict__ Whi, const __half* __restrict__ Wlo,
    const float* __restrict__ bias,
    float* __restrict__ Cf, __half* __restrict__ Chi, __half* __restrict__ Clo,
    int N, int K)
{
    extern __shared__ char smem[];
    const int tid = threadIdx.x;
    const int wid = tid >> 5, lane = tid & 31;
    const int wm = wid & 3, wn = wid >> 2;
    const long rowBase = (long)blockIdx.y * 128;
    const int  colBase = blockIdx.x * 128;

    float acc[2][8][4];
#pragma unroll
    for (int i = 0; i < 2; i++)
#pragma unroll
        for (int j = 0; j < 8; j++)
#pragma unroll
            for (int e = 0; e < 4; e++) acc[i][j][e] = 0.f;

    const uint32_t sb0 = smem_u32(smem);
    uint32_t aAddr[2], bAddr[4];
#pragma unroll
    for (int mf = 0; mf < 2; mf++)
        aAddr[mf] = sb0 + (uint32_t)(((wm * 32 + mf * 16 + (lane & 15)) * SAW2
                                      + (lane >> 4) * 8) * 2);
#pragma unroll
    for (int ng = 0; ng < 4; ng++)
        bAddr[ng] = sb0 + SMEM_A2 + (uint32_t)(((lane & 15) * SBW
                                      + wn * 64 + ng * 16 + (lane >> 4) * 8) * 2);

    const int nch = K / 32;

    auto loadTiles = [&](int ch, int st) {
        const int kt = ch * 32;
        const uint32_t sbA = sb0 + st * SM_STAGE2;
        const uint32_t sbB = sbA + SMEM_A2;
#pragma unroll
        for (int i = 0; i < 4; i++) {
            int lin = tid + i * 256;
            int row = lin >> 4, u = lin & 15;
            const __half* src = ((row >= 32) ? Wlo : Whi)
                + (long)(kt + (row & 31)) * N + colBase + u * 8;
            cpa16(sbB + (uint32_t)(row * SBW + u * 8) * 2, src);
        }
        if (ASPLIT) {
            const int r = tid >> 1, q = tid & 1;
            const __half* sh = Ahi + (rowBase + r) * (long)K + kt + q * 16;
            const __half* sl = Alo + (rowBase + r) * (long)K + kt + q * 16;
            uint32_t dh = sbA + (uint32_t)(r * SAW2 + q * 16) * 2;
            uint32_t dl = sbA + (uint32_t)(r * SAW2 + 32 + q * 16) * 2;
            cpa16(dh, sh);      cpa16(dh + 16, sh + 8);
            cpa16(dl, sl);      cpa16(dl + 16, sl + 8);
        } else {
            const float* Ap; int sA_, kof;
            if (kt < K0) { Ap = A0f; sA_ = sA0; kof = kt; }
            else         { Ap = A1f; sA_ = sA1; kof = kt - K0; }
            const int r = tid >> 1, q = tid & 1;
            const float4* src = reinterpret_cast<const float4*>(
                Ap + (rowBase + r) * (long)sA_ + kof + q * 16);
            __half* rowp = reinterpret_cast<__half*>(smem + st * SM_STAGE2)
                           + r * SAW2;
#pragma unroll
            for (int j = 0; j < 4; j++) {
                float4 v = src[j];
                int c = q * 16 + j * 4;
                __half hx = __float2half_rn(v.x), hy = __float2half_rn(v.y);
                __half hz = __float2half_rn(v.z), hw = __float2half_rn(v.w);
                __half lx = __float2half_rn(v.x - __half2float(hx));
                __half ly = __float2half_rn(v.y - __half2float(hy));
                __half lz = __float2half_rn(v.z - __half2float(hz));
                __half lw = __float2half_rn(v.w - __half2float(hw));
                __half2 h01 = __halves2half2(hx, hy), h23 = __halves2half2(hz, hw);
                __half2 l01 = __halves2half2(lx, ly), l23 = __halves2half2(lz, lw);
                *reinterpret_cast<uint2*>(rowp + c) =
                    make_uint2(*(uint32_t*)&h01, *(uint32_t*)&h23);
                *reinterpret_cast<uint2*>(rowp + 32 + c) =
                    make_uint2(*(uint32_t*)&l01, *(uint32_t*)&l23);
            }
        }
    };

    loadTiles(0, 0);
    cpa_commit();

    for (int ch = 0; ch < nch; ch++) {
        cpa_wait0();
        __syncthreads();
        if (ch + 1 < nch) { loadTiles(ch + 1, (ch + 1) & 1); cpa_commit(); }

        const uint32_t so = (uint32_t)((ch & 1) * SM_STAGE2);
        const int aof[6] = {0, 16, 32, 48, 0, 16};
        const int bof[6] = {0, 16, 0, 16, 32, 48};
#pragma unroll
        for (int s = 0; s < 6; s++) {
            uint32_t afr[2][4];
            ldsm_x4(afr[0], aAddr[0] + so + aof[s] * 2);
            ldsm_x4(afr[1], aAddr[1] + so + aof[s] * 2);
            uint32_t bfr[4][4];
#pragma unroll
            for (int ng = 0; ng < 4; ng++)
                ldsm_x4_t(bfr[ng], bAddr[ng] + so + bof[s] * SBW * 2);
#pragma unroll
            for (int ng = 0; ng < 4; ng++) {
#pragma unroll
                for (int mf = 0; mf < 2; mf++) {
                    mma16816(acc[mf][ng * 2],     afr[mf], bfr[ng][0], bfr[ng][1]);
                    mma16816(acc[mf][ng * 2 + 1], afr[mf], bfr[ng][2], bfr[ng][3]);
                }
            }
        }
    }

    // ---- epilogue ----
#pragma unroll
    for (int mf = 0; mf < 2; mf++) {
        long row = rowBase + wm * 32 + mf * 16 + (lane >> 2);
#pragma unroll
        for (int nf = 0; nf < 8; nf++) {
            int col = colBase + wn * 64 + nf * 8 + (lane & 3) * 2;
            float bx = bias[col], by = bias[col + 1];
            float v0 = acc[mf][nf][0] + bx, v1 = acc[mf][nf][1] + by;
            float v2 = acc[mf][nf][2] + bx, v3 = acc[mf][nf][3] + by;
            if (OSPLIT) {
                __half h0 = __float2half_rn(v0), h1 = __float2half_rn(v1);
                __half h2 = __float2half_rn(v2), h3 = __float2half_rn(v3);
                __half2 hi0 = __halves2half2(h0, h1), hi1 = __halves2half2(h2, h3);
                __half2 lo0 = __halves2half2(
                    __float2half_rn(v0 - __half2float(h0)),
                    __float2half_rn(v1 - __half2float(h1)));
                __half2 lo1 = __halves2half2(
                    __float2half_rn(v2 - __half2float(h2)),
                    __float2half_rn(v3 - __half2float(h3)));
                *reinterpret_cast<__half2*>(Chi + row * (long)N + col) = hi0;
                *reinterpret_cast<__half2*>(Clo + row * (long)N + col) = lo0;
                *reinterpret_cast<__half2*>(Chi + (row + 8) * (long)N + col) = hi1;
                *reinterpret_cast<__half2*>(Clo + (row + 8) * (long)N + col) = lo1;
            } else {
                *reinterpret_cast<float2*>(Cf + row * (long)N + col) =
                    make_float2(v0, v1);
                *reinterpret_cast<float2*>(Cf + (row + 8) * (long)N + col) =
                    make_float2(v2, v3);
            }
        }
    }
}

// ---------------- depthwise causal conv + SiLU, rolling window ------------
// thread = (16-token chunk, d). 16 | L so chunks never cross sequences.
__global__ void conv_silu_kernel(const float* __restrict__ xz,
                                 const float* __restrict__ cw,
                                 const float* __restrict__ cb,
                                 float* __restrict__ xc)
{
    int gid = blockIdx.x * 256 + threadIdx.x;   // 0 .. 1048575
    int d = gid & 255;
    long tb = (long)(gid >> 8) * 16;            // token base
    int l = (int)(tb & (L_ - 1));

    const float w0 = cw[d * 4 + 0], w1 = cw[d * 4 + 1];
    const float w2 = cw[d * 4 + 2], w3 = cw[d * 4 + 3];
    const float cbd = cb[d];

    float x3 = 0.f, x2 = 0.f, x1 = 0.f;
    if (l > 0) {            // l is a multiple of 16, so l >= 16 > 3 here
        x3 = xz[(tb - 3) * 512 + d];
        x2 = xz[(tb - 2) * 512 + d];
        x1 = xz[(tb - 1) * 512 + d];
    }
#pragma unroll
    for (int t = 0; t < 16; t++) {
        float xt = xz[(tb + t) * 512 + d];
        float a = cbd + w0 * x3 + w1 * x2 + w2 * x1 + w3 * xt;
        float s = 1.f / (1.f + __expf(-a));
        xc[(tb + t) * 256 + d] = a * s;
        x3 = x2; x2 = x1; x1 = xt;
    }
}

// ---------------- xc @ W_xproj (K=256, N=40) ------------------------------
__global__ __launch_bounds__(256) void xproj_kernel(
    const float* __restrict__ Ain, const float* __restrict__ W,
    float* __restrict__ outp)
{
    constexpr int BK = 32;
    __shared__ float As[BK][128 + 4];
    __shared__ float Bs[BK][40];
    const int tid = threadIdx.x;
    const int tx = tid & 7;
    const int ty = tid >> 3;
    const long rowBase = (long)blockIdx.x * 128;

    float acc[4][5];
#pragma unroll
    for (int i = 0; i < 4; i++)
#pragma unroll
        for (int j = 0; j < 5; j++) acc[i][j] = 0.f;

    for (int kt = 0; kt < 256; kt += BK) {
#pragma unroll
        for (int i = 0; i < 4; i++) {
            int lin = tid + i * 256;
            int r   = lin >> 3;
            int k4  = (lin & 7) * 4;
            float4 v = *reinterpret_cast<const float4*>(Ain + (rowBase + r) * 256 + kt + k4);
            As[k4 + 0][r] = v.x; As[k4 + 1][r] = v.y;
            As[k4 + 2][r] = v.z; As[k4 + 3][r] = v.w;
        }
#pragma unroll
        for (int i = 0; i < 5; i++) {
            int lin = tid + i * 256;
            int kr = lin / 40, c = lin % 40;
            Bs[kr][c] = W[(kt + kr) * 40 + c];
        }
        __syncthreads();
#pragma unroll
        for (int k = 0; k < BK; k++) {
            float a[4], b[5];
            *reinterpret_cast<float4*>(&a[0]) = *reinterpret_cast<float4*>(&As[k][ty * 4]);
#pragma unroll
            for (int j = 0; j < 5; j++) b[j] = Bs[k][tx * 5 + j];
#pragma unroll
            for (int i = 0; i < 4; i++)
#pragma unroll
                for (int j = 0; j < 5; j++) acc[i][j] += a[i] * b[j];
        }
        __syncthreads();
    }
#pragma unroll
    for (int i = 0; i < 4; i++) {
        long row = rowBase + ty * 4 + i;
#pragma unroll
        for (int j = 0; j < 5; j++) outp[row * 40 + tx * 5 + j] = acc[i][j];
    }
}

// ---------------- scan phase A (dt recomputed in-kernel) ------------------
__global__ __launch_bounds__(256) void scanA_kernel(
    const float* __restrict__ xcg, const float* __restrict__ dbl,
    const float* __restrict__ W_dt, const float* __restrict__ b_dt,
    const float* __restrict__ A_log,
    float* __restrict__ hloc, float* __restrict__ sumdtArr)
{
    const int bid = blockIdx.x;
    const int b = bid / NC, c = bid % NC;
    const long mbase = (long)b * L_ + (long)c * CL;
    const int d = threadIdx.x;

    float Ar[16]; bool fast = true;
#pragma unroll
    for (int s = 0; s < 16; s++) {
        Ar[s] = -__expf(A_log[d * 16 + s]);
        float n = (float)(s + 1);
        fast = fast && (fabsf(Ar[s] + n) < 1e-3f * n);
    }
    float wdt[8];
#pragma unroll
    for (int k = 0; k < 8; k++) wdt[k] = W_dt[k * 256 + d];
    const float bb = b_dt[d];

    __shared__ float sB[CL][16];
    __shared__ float sD[CL][8];
#pragma unroll
    for (int i = 0; i < 4; i++) {
        int lin = threadIdx.x + i * 256;
        sB[lin >> 4][lin & 15] = dbl[(mbase + (lin >> 4)) * 40 + 8 + (lin & 15)];
    }
#pragma unroll
    for (int i = 0; i < 2; i++) {
        int lin = threadIdx.x + i * 256;
        sD[lin >> 3][lin & 7] = dbl[(mbase + (lin >> 3)) * 40 + (lin & 7)];
    }
    __syncthreads();

    float h[16];
#pragma unroll
    for (int s = 0; s < 16; s++) h[s] = 0.f;
    float sumdt = 0.f;

    for (int t = 0; t < CL; t++) {
        long m = mbase + t;
        float pre = bb;
#pragma unroll
        for (int k = 0; k < 8; k++) pre += sD[t][k] * wdt[k];
        float e = __expf(pre);
        float dtv = (pre > 15.f) ? pre : __logf(1.f + e);
        float p = __fdividef(1.f, 1.f + e);       // exp(-softplus(pre))
        float xv = xcg[m * 256 + d];
        sumdt += dtv;
        float cc = dtv * xv;
        float pw[16];
        if (fast) {
            float p2 = p * p, p4 = p2 * p2, p8 = p4 * p4;
            pw[0] = p;        pw[1] = p2;       pw[2] = p2 * p;    pw[3] = p4;
            pw[4] = p4 * p;   pw[5] = p4 * p2;  pw[6] = p4 * pw[2];
            pw[7] = p8;       pw[8] = p8 * p;   pw[9] = p8 * p2;   pw[10] = p8 * pw[2];
            pw[11] = p8 * p4; pw[12] = p8 * pw[4]; pw[13] = p8 * pw[5];
            pw[14] = p8 * pw[6]; pw[15] = p8 * p8;
        } else {
#pragma unroll
            for (int s = 0; s < 16; s++) pw[s] = __expf(dtv * Ar[s]);
        }
#pragma unroll
        for (int s = 0; s < 16; s++) h[s] = pw[s] * h[s] + cc * sB[t][s];
    }

    long o = ((long)bid * 256 + d) * 16;
#pragma unroll
    for (int s = 0; s < 16; s += 4)
        *reinterpret_cast<float4*>(hloc + o + s) =
            make_float4(h[s], h[s + 1], h[s + 2], h[s + 3]);
    sumdtArr[(long)bid * 256 + d] = sumdt;
}

// ---------------- scan phase B ------------------------------------------
__global__ void scanB_kernel(const float* __restrict__ hloc,
                             const float* __restrict__ sumdtArr,
                             const float* __restrict__ A_log,
                             float* __restrict__ hin)
{
    int gid = blockIdx.x * 256 + threadIdx.x;
    int b = gid >> 12;
    int r = gid & 4095;
    int d = r >> 4, s = r & 15;
    float As_ = -__expf(A_log[d * 16 + s]);
    float h = 0.f;
    for (int c = 0; c < NC; c++) {
        long idx = ((long)(b * NC + c) * 256 + d);
        hin[idx * 16 + s] = h;
        float pw = __expf(As_ * sumdtArr[idx]);
        h = pw * h + hloc[idx * 16 + s];
    }
}

// ---------------- scan phase C: replay + gate, dt recomputed --------------
__global__ __launch_bounds__(256) void scanC_kernel(
    const float* __restrict__ xcg, const float* __restrict__ xz,
    const float* __restrict__ dbl,
    const float* __restrict__ W_dt, const float* __restrict__ b_dt,
    const float* __restrict__ A_log, const float* __restrict__ Dp,
    const float* __restrict__ hin,
    __half* __restrict__ yhi, __half* __restrict__ ylo)
{
    const int bid = blockIdx.x;
    const int b = bid / NC, c = bid % NC;
    const long mbase = (long)b * L_ + (long)c * CL;
    const int d = threadIdx.x;

    float Ar[16]; bool fast = true;
#pragma unroll
    for (int s = 0; s < 16; s++) {
        Ar[s] = -__expf(A_log[d * 16 + s]);
        float n = (float)(s + 1);
        fast = fast && (fabsf(Ar[s] + n) < 1e-3f * n);
    }
    float wdt[8];
#pragma unroll
    for (int k = 0; k < 8; k++) wdt[k] = W_dt[k * 256 + d];
    const float bb = b_dt[d];

    __shared__ float sB[CL][16];
    __shared__ float sC[CL][16];
    __shared__ float sD[CL][8];
#pragma unroll
    for (int i = 0; i < 4; i++) {
        int lin = threadIdx.x + i * 256;
        long mm = mbase + (lin >> 4);
        sB[lin >> 4][lin & 15] = dbl[mm * 40 + 8  + (lin & 15)];
        sC[lin >> 4][lin & 15] = dbl[mm * 40 + 24 + (lin & 15)];
    }
#pragma unroll
    for (int i = 0; i < 2; i++) {
        int lin = threadIdx.x + i * 256;
        sD[lin >> 3][lin & 7] = dbl[(mbase + (lin >> 3)) * 40 + (lin & 7)];
    }
    __syncthreads();

    float h[16];
    long o = ((long)bid * 256 + d) * 16;
#pragma unroll
    for (int s = 0; s < 16; s += 4) {
        float4 v = *reinterpret_cast<const float4*>(hin + o + s);
        h[s] = v.x; h[s + 1] = v.y; h[s + 2] = v.z; h[s + 3] = v.w;
    }
    const float Dd = Dp[d];

    for (int t = 0; t < CL; t++) {
        long m = mbase + t;
        float pre = bb;
#pragma unroll
        for (int k = 0; k < 8; k++) pre += sD[t][k] * wdt[k];
        float e = __expf(pre);
        float dtv = (pre > 15.f) ? pre : __logf(1.f + e);
        float p = __fdividef(1.f, 1.f + e);
        float xv = xcg[m * 256 + d];
        float cc = dtv * xv;
        float pw[16];
        if (fast) {
            float p2 = p * p, p4 = p2 * p2, p8 = p4 * p4;
            pw[0] = p;        pw[1] = p2;       pw[2] = p2 * p;    pw[3] = p4;
            pw[4] = p4 * p;   pw[5] = p4 * p2;  pw[6] = p4 * pw[2];
            pw[7] = p8;       pw[8] = p8 * p;   pw[9] = p8 * p2;   pw[10] = p8 * pw[2];
            pw[11] = p8 * p4; pw[12] = p8 * pw[4]; pw[13] = p8 * pw[5];
            pw[14] = p8 * pw[6]; pw[15] = p8 * p8;
        } else {
#pragma unroll
            for (int s = 0; s < 16; s++) pw[s] = __expf(dtv * Ar[s]);
        }
        float y = 0.f;
#pragma unroll
        for (int s = 0; s < 16; s++) {
            h[s] = pw[s] * h[s] + cc * sB[t][s];
            y += h[s] * sC[t][s];
        }
        float zv = xz[m * 512 + 256 + d];
        float sg = 1.f / (1.f + __expf(-zv));
        float v = (y + xv * Dd) * (zv * sg);
        __half hh = __float2half_rn(v);
        yhi[m * 256 + d] = hh;
        ylo[m * 256 + d] = __float2half_rn(v - __half2float(hh));
    }
}

// ---------------- launcher (stateless, call-invariant) --------------------
extern "C" void kernel_launch(void* const* d_in, const int* in_sizes, int n_in,
                              void* d_out, int out_size)
{
    const float* x      = (const float*)d_in[0];
    const float* qk     = (const float*)d_in[1];
    const float* W_mix  = (const float*)d_in[2];
    const float* b_mix  = (const float*)d_in[3];
    const float* W_in   = (const float*)d_in[4];
    const float* b_in   = (const float*)d_in[5];
    const float* conv_w = (const float*)d_in[6];
    const float* conv_b = (const float*)d_in[7];
    const float* W_xproj= (const float*)d_in[8];
    const float* W_dt   = (const float*)d_in[9];
    const float* b_dt   = (const float*)d_in[10];
    const float* A_log  = (const float*)d_in[11];
    const float* D_param= (const float*)d_in[12];
    const float* W_op   = (const float*)d_in[13];
    const float* b_op   = (const float*)d_in[14];
    const float* W_out  = (const float*)d_in[15];
    const float* b_out  = (const float*)d_in[16];
    float* out = (float*)d_out;

    float  *pxz, *pxc, *pdbl, *phloc, *phin, *psum;
    __half *phhi, *phlo, *pyhi, *pylo, *pt1hi, *pt1lo;
    __half *pwmixh, *pwmixl, *pwinh, *pwinl, *pwoph, *pwopl, *pwouth, *pwoutl;
    cudaGetSymbolAddress((void**)&pxz,   g_xz);
    cudaGetSymbolAddress((void**)&pxc,   g_xc);
    cudaGetSymbolAddress((void**)&pdbl,  g_dbl);
    cudaGetSymbolAddress((void**)&phloc, g_hloc);
    cudaGetSymbolAddress((void**)&phin,  g_hin);
    cudaGetSymbolAddress((void**)&psum,  g_sumdt);
    cudaGetSymbolAddress((void**)&phhi,  g_h_hi);
    cudaGetSymbolAddress((void**)&phlo,  g_h_lo);
    cudaGetSymbolAddress((void**)&pyhi,  g_yf_hi);
    cudaGetSymbolAddress((void**)&pylo,  g_yf_lo);
    cudaGetSymbolAddress((void**)&pt1hi, g_t1_hi);
    cudaGetSymbolAddress((void**)&pt1lo, g_t1_lo);
    cudaGetSymbolAddress((void**)&pwmixh, g_wmix_hi);
    cudaGetSymbolAddress((void**)&pwmixl, g_wmix_lo);
    cudaGetSymbolAddress((void**)&pwinh,  g_win_hi);
    cudaGetSymbolAddress((void**)&pwinl,  g_win_lo);
    cudaGetSymbolAddress((void**)&pwoph,  g_wop_hi);
    cudaGetSymbolAddress((void**)&pwopl,  g_wop_lo);
    cudaGetSymbolAddress((void**)&pwouth, g_wout_hi);
    cudaGetSymbolAddress((void**)&pwoutl, g_wout_lo);
    cudaFuncSetAttribute(tcgemm2<false, true>,
        cudaFuncAttributeMaxDynamicSharedMemorySize, GEMM_SMEM2);
    cudaFuncSetAttribute(tcgemm2<true, false>,
        cudaFuncAttributeMaxDynamicSharedMemorySize, GEMM_SMEM2);
    cudaFuncSetAttribute(tcgemm2<true, true>,
        cudaFuncAttributeMaxDynamicSharedMemorySize, GEMM_SMEM2);

    dim3 blk(256);
    // all four weight splits in one launch (196608 elements)
    split_all<<<768, 256>>>(W_mix, W_in, W_op, W_out,
                            pwmixh, pwmixl, pwinh, pwinl,
                            pwoph, pwopl, pwouth, pwoutl);

    // h = concat(x,qk) @ W_mix + b_mix  -> fp16 hi/lo   [65536,128], K=512
    tcgemm2<false, true><<<dim3(1, 512), blk, GEMM_SMEM2>>>(
        x, qk, 256, 256, 256, nullptr, nullptr,
        pwmixh, pwmixl, b_mix, nullptr, phhi, phlo, 128, 512);
    // xz = h @ W_in + b_in  -> fp32                      [65536,512], K=128
    tcgemm2<true, false><<<dim3(4, 512), blk, GEMM_SMEM2>>>(
        nullptr, nullptr, 0, 0, 0, phhi, phlo,
        pwinh, pwinl, b_in, pxz, nullptr, nullptr, 512, 128);
    // xc = silu(causal_conv(xz[:, :256])) — rolling window
    conv_silu_kernel<<<4096, 256>>>(pxz, conv_w, conv_b, pxc);
    // dbl = xc @ W_xproj                                  [65536,40]
    xproj_kernel<<<512, 256>>>(pxc, W_xproj, pdbl);
    // chunked selective scan (dt recomputed in-kernel from dbl)
    scanA_kernel<<<B_ * NC, 256>>>(pxc, pdbl, W_dt, b_dt, A_log, phloc, psum);
    scanB_kernel<<<256, 256>>>(phloc, psum, A_log, phin);
    scanC_kernel<<<B_ * NC, 256>>>(pxc, pxz, pdbl, W_dt, b_dt, A_log, D_param,
                                   phin, pyhi, pylo);
    // t1 = yf @ W_op + b_op  -> fp16 hi/lo                [65536,128], K=256
    tcgemm2<true, true><<<dim3(1, 512), blk, GEMM_SMEM2>>>(
        nullptr, nullptr, 0, 0, 0, pyhi, pylo,
        pwoph, pwopl, b_op, nullptr, pt1hi, pt1lo, 128, 256);
    // out = t1 @ W_out + b_out -> fp32                    [65536,256], K=128
    tcgemm2<true, false><<<dim3(2, 512), blk, GEMM_SMEM2>>>(
        nullptr, nullptr, 0, 0, 0, pt1hi, pt1lo,
        pwouth, pwoutl, b_out, out, nullptr, nullptr, 256, 128);
}

// round 13
// speedup vs baseline: 1.1644x; 1.0088x over previous
#include <cuda_runtime.h>
#include <cuda_fp16.h>
#include <math.h>
#include <stdint.h>

// Problem constants
constexpr int B_  = 16;
constexpr int L_  = 4096;
constexpr int DI  = 256;   // D_INNER
constexpr int DS  = 16;    // D_STATE
constexpr long BLD = (long)B_ * L_;   // 65536 tokens

constexpr int CL  = 64;          // chunk length for scan
constexpr int NC  = L_ / CL;     // 64 chunks

// ---------------- scratch (device globals; no allocation) ----------------
__device__ float  g_xz  [BLD * 512];      // after W_in (xc_raw | z)
__device__ float  g_xc  [BLD * DI];       // after conv+silu
__device__ float  g_dbl [BLD * 40];       // xproj output (dtrank|B|C)
__device__ float  g_hloc[(long)B_ * NC * DI * DS];
__device__ float  g_hin [(long)B_ * NC * DI * DS];
__device__ float  g_sumdt[(long)B_ * NC * DI];
// fp16 hi/lo activation carries
__device__ __half g_h_hi [BLD * 128];
__device__ __half g_h_lo [BLD * 128];
__device__ __half g_yf_hi[BLD * 256];
__device__ __half g_yf_lo[BLD * 256];
__device__ __half g_t1_hi[BLD * 128];
__device__ __half g_t1_lo[BLD * 128];
// fp16 hi/lo weights
__device__ __half g_wmix_hi[512 * 128], g_wmix_lo[512 * 128];
__device__ __half g_win_hi [128 * 512], g_win_lo [128 * 512];
__device__ __half g_wop_hi [256 * 128], g_wop_lo [256 * 128];
__device__ __half g_wout_hi[128 * 256], g_wout_lo[128 * 256];

// ======================= helpers =========================================
__device__ __forceinline__ uint32_t smem_u32(const void* p) {
    uint32_t a;
    asm("{ .reg .u64 t; cvta.to.shared.u64 t, %1; cvt.u32.u64 %0, t; }"
        : "=r"(a) : "l"(p));
    return a;
}
__device__ __forceinline__ void cpa16(uint32_t dst, const void* src) {
    asm volatile("cp.async.cg.shared.global [%0], [%1], 16;"
                 :: "r"(dst), "l"(src) : "memory");
}
__device__ __forceinline__ void cpa_commit() {
    asm volatile("cp.async.commit_group;" ::: "memory");
}
__device__ __forceinline__ void cpa_wait0() {
    asm volatile("cp.async.wait_group 0;" ::: "memory");
}
__device__ __forceinline__ void ldsm_x4(uint32_t* r, uint32_t addr) {
    asm volatile("ldmatrix.sync.aligned.m8n8.x4.shared.b16 {%0,%1,%2,%3}, [%4];"
        : "=r"(r[0]), "=r"(r[1]), "=r"(r[2]), "=r"(r[3]) : "r"(addr));
}
__device__ __forceinline__ void ldsm_x4_t(uint32_t* r, uint32_t addr) {
    asm volatile("ldmatrix.sync.aligned.m8n8.x4.trans.shared.b16 {%0,%1,%2,%3}, [%4];"
        : "=r"(r[0]), "=r"(r[1]), "=r"(r[2]), "=r"(r[3]) : "r"(addr));
}
__device__ __forceinline__ void mma16816(float* c, const uint32_t* a,
                                         uint32_t b0, uint32_t b1) {
    asm volatile("mma.sync.aligned.m16n8k16.row.col.f32.f16.f16.f32 "
        "{%0,%1,%2,%3}, {%4,%5,%6,%7}, {%8,%9}, {%0,%1,%2,%3};"
        : "+f"(c[0]), "+f"(c[1]), "+f"(c[2]), "+f"(c[3])
        : "r"(a[0]), "r"(a[1]), "r"(a[2]), "r"(a[3]), "r"(b0), "r"(b1));
}

// ---------------- fused weight splitter (all 4 weights, one launch) -------
__global__ void split_all(const float* __restrict__ Wmix,
                          const float* __restrict__ Win,
                          const float* __restrict__ Wop,
                          const float* __restrict__ Wout,
                          __half* __restrict__ mh, __half* __restrict__ ml,
                          __half* __restrict__ ih, __half* __restrict__ il,
                          __half* __restrict__ oh, __half* __restrict__ ol,
                          __half* __restrict__ uh, __half* __restrict__ ul)
{
    int i = blockIdx.x * 256 + threadIdx.x;   // 0..196607
    const float* src; __half *dh, *dl; int j;
    if (i < 65536)        { src = Wmix; dh = mh; dl = ml; j = i; }
    else if (i < 131072)  { src = Win;  dh = ih; dl = il; j = i - 65536; }
    else if (i < 163840)  { src = Wop;  dh = oh; dl = ol; j = i - 131072; }
    else                  { src = Wout; dh = uh; dl = ul; j = i - 163840; }
    float v = src[j];
    __half h = __float2half_rn(v);
    dh[j] = h;
    dl[j] = __float2half_rn(v - __half2float(h));
}

// ====== tensor-core GEMM (mma.sync, fp16 hi/lo, compact smem) ============
constexpr int SAW2 = 72;
constexpr int SBW  = 136;
constexpr int SMEM_A2 = 128 * SAW2 * 2;    // 18432
constexpr int SMEM_B2 = 64 * SBW * 2;      // 17408
constexpr int SM_STAGE2 = SMEM_A2 + SMEM_B2;   // 35840
constexpr int GEMM_SMEM2 = 2 * SM_STAGE2;      // 71680

template<bool ASPLIT, bool OSPLIT>
__global__ __launch_bounds__(256) void tcgemm2(
    const float* __restrict__ A0f, const float* __restrict__ A1f,
    int K0, int sA0, int sA1,
    const __half* __restrict__ Ahi, const __half* __restrict__ Alo,
    const __half* __restrict__ Whi, const __half* __restrict__ Wlo,
    const float* __restrict__ bias,
    float* __restrict__ Cf, __half* __restrict__ Chi, __half* __restrict__ Clo,
    int N, int K)
{
    extern __shared__ char smem[];
    const int tid = threadIdx.x;
    const int wid = tid >> 5, lane = tid & 31;
    const int wm = wid & 3, wn = wid >> 2;
    const long rowBase = (long)blockIdx.y * 128;
    const int  colBase = blockIdx.x * 128;

    float acc[2][8][4];
#pragma unroll
    for (int i = 0; i < 2; i++)
#pragma unroll
        for (int j = 0; j < 8; j++)
#pragma unroll
            for (int e = 0; e < 4; e++) acc[i][j][e] = 0.f;

    const uint32_t sb0 = smem_u32(smem);
    uint32_t aAddr[2], bAddr[4];
#pragma unroll
    for (int mf = 0; mf < 2; mf++)
        aAddr[mf] = sb0 + (uint32_t)(((wm * 32 + mf * 16 + (lane & 15)) * SAW2
                                      + (lane >> 4) * 8) * 2);
#pragma unroll
    for (int ng = 0; ng < 4; ng++)
        bAddr[ng] = sb0 + SMEM_A2 + (uint32_t)(((lane & 15) * SBW
                                      + wn * 64 + ng * 16 + (lane >> 4) * 8) * 2);

    const int nch = K / 32;

    auto loadTiles = [&](int ch, int st) {
        const int kt = ch * 32;
        const uint32_t sbA = sb0 + st * SM_STAGE2;
        const uint32_t sbB = sbA + SMEM_A2;
#pragma unroll
        for (int i = 0; i < 4; i++) {
            int lin = tid + i * 256;
            int row = lin >> 4, u = lin & 15;
            const __half* src = ((row >= 32) ? Wlo : Whi)
                + (long)(kt + (row & 31)) * N + colBase + u * 8;
            cpa16(sbB + (uint32_t)(row * SBW + u * 8) * 2, src);
        }
        if (ASPLIT) {
            const int r = tid >> 1, q = tid & 1;
            const __half* sh = Ahi + (rowBase + r) * (long)K + kt + q * 16;
            const __half* sl = Alo + (rowBase + r) * (long)K + kt + q * 16;
            uint32_t dh = sbA + (uint32_t)(r * SAW2 + q * 16) * 2;
            uint32_t dl = sbA + (uint32_t)(r * SAW2 + 32 + q * 16) * 2;
            cpa16(dh, sh);      cpa16(dh + 16, sh + 8);
            cpa16(dl, sl);      cpa16(dl + 16, sl + 8);
        } else {
            const float* Ap; int sA_, kof;
            if (kt < K0) { Ap = A0f; sA_ = sA0; kof = kt; }
            else         { Ap = A1f; sA_ = sA1; kof = kt - K0; }
            const int r = tid >> 1, q = tid & 1;
            const float4* src = reinterpret_cast<const float4*>(
                Ap + (rowBase + r) * (long)sA_ + kof + q * 16);
            __half* rowp = reinterpret_cast<__half*>(smem + st * SM_STAGE2)
                           + r * SAW2;
#pragma unroll
            for (int j = 0; j < 4; j++) {
                float4 v = src[j];
                int c = q * 16 + j * 4;
                __half hx = __float2half_rn(v.x), hy = __float2half_rn(v.y);
                __half hz = __float2half_rn(v.z), hw = __float2half_rn(v.w);
                __half lx = __float2half_rn(v.x - __half2float(hx));
                __half ly = __float2half_rn(v.y - __half2float(hy));
                __half lz = __float2half_rn(v.z - __half2float(hz));
                __half lw = __float2half_rn(v.w - __half2float(hw));
                __half2 h01 = __halves2half2(hx, hy), h23 = __halves2half2(hz, hw);
                __half2 l01 = __halves2half2(lx, ly), l23 = __halves2half2(lz, lw);
                *reinterpret_cast<uint2*>(rowp + c) =
                    make_uint2(*(uint32_t*)&h01, *(uint32_t*)&h23);
                *reinterpret_cast<uint2*>(rowp + 32 + c) =
                    make_uint2(*(uint32_t*)&l01, *(uint32_t*)&l23);
            }
        }
    };

    loadTiles(0, 0);
    cpa_commit();

    for (int ch = 0; ch < nch; ch++) {
        cpa_wait0();
        __syncthreads();
        if (ch + 1 < nch) { loadTiles(ch + 1, (ch + 1) & 1); cpa_commit(); }

        const uint32_t so = (uint32_t)((ch & 1) * SM_STAGE2);
        const int aof[6] = {0, 16, 32, 48, 0, 16};
        const int bof[6] = {0, 16, 0, 16, 32, 48};
#pragma unroll
        for (int s = 0; s < 6; s++) {
            uint32_t afr[2][4];
            ldsm_x4(afr[0], aAddr[0] + so + aof[s] * 2);
            ldsm_x4(afr[1], aAddr[1] + so + aof[s] * 2);
            uint32_t bfr[4][4];
#pragma unroll
            for (int ng = 0; ng < 4; ng++)
                ldsm_x4_t(bfr[ng], bAddr[ng] + so + bof[s] * SBW * 2);
#pragma unroll
            for (int ng = 0; ng < 4; ng++) {
#pragma unroll
                for (int mf = 0; mf < 2; mf++) {
                    mma16816(acc[mf][ng * 2],     afr[mf], bfr[ng][0], bfr[ng][1]);
                    mma16816(acc[mf][ng * 2 + 1], afr[mf], bfr[ng][2], bfr[ng][3]);
                }
            }
        }
    }

    // ---- epilogue ----
#pragma unroll
    for (int mf = 0; mf < 2; mf++) {
        long row = rowBase + wm * 32 + mf * 16 + (lane >> 2);
#pragma unroll
        for (int nf = 0; nf < 8; nf++) {
            int col = colBase + wn * 64 + nf * 8 + (lane & 3) * 2;
            float bx = bias[col], by = bias[col + 1];
            float v0 = acc[mf][nf][0] + bx, v1 = acc[mf][nf][1] + by;
            float v2 = acc[mf][nf][2] + bx, v3 = acc[mf][nf][3] + by;
            if (OSPLIT) {
                __half h0 = __float2half_rn(v0), h1 = __float2half_rn(v1);
                __half h2 = __float2half_rn(v2), h3 = __float2half_rn(v3);
                __half2 hi0 = __halves2half2(h0, h1), hi1 = __halves2half2(h2, h3);
                __half2 lo0 = __halves2half2(
                    __float2half_rn(v0 - __half2float(h0)),
                    __float2half_rn(v1 - __half2float(h1)));
                __half2 lo1 = __halves2half2(
                    __float2half_rn(v2 - __half2float(h2)),
                    __float2half_rn(v3 - __half2float(h3)));
                *reinterpret_cast<__half2*>(Chi + row * (long)N + col) = hi0;
                *reinterpret_cast<__half2*>(Clo + row * (long)N + col) = lo0;
                *reinterpret_cast<__half2*>(Chi + (row + 8) * (long)N + col) = hi1;
                *reinterpret_cast<__half2*>(Clo + (row + 8) * (long)N + col) = lo1;
            } else {
                *reinterpret_cast<float2*>(Cf + row * (long)N + col) =
                    make_float2(v0, v1);
                *reinterpret_cast<float2*>(Cf + (row + 8) * (long)N + col) =
                    make_float2(v2, v3);
            }
        }
    }
}

// ---------------- depthwise causal conv + SiLU, rolling window ------------
__global__ void conv_silu_kernel(const float* __restrict__ xz,
                                 const float* __restrict__ cw,
                                 const float* __restrict__ cb,
                                 float* __restrict__ xc)
{
    int gid = blockIdx.x * 256 + threadIdx.x;   // 0 .. 1048575
    int d = gid & 255;
    long tb = (long)(gid >> 8) * 16;            // token base
    int l = (int)(tb & (L_ - 1));

    const float w0 = cw[d * 4 + 0], w1 = cw[d * 4 + 1];
    const float w2 = cw[d * 4 + 2], w3 = cw[d * 4 + 3];
    const float cbd = cb[d];

    float x3 = 0.f, x2 = 0.f, x1 = 0.f;
    if (l > 0) {
        x3 = xz[(tb - 3) * 512 + d];
        x2 = xz[(tb - 2) * 512 + d];
        x1 = xz[(tb - 1) * 512 + d];
    }
#pragma unroll
    for (int t = 0; t < 16; t++) {
        float xt = xz[(tb + t) * 512 + d];
        float a = cbd + w0 * x3 + w1 * x2 + w2 * x1 + w3 * xt;
        float s = 1.f / (1.f + __expf(-a));
        xc[(tb + t) * 256 + d] = a * s;
        x3 = x2; x2 = x1; x1 = xt;
    }
}

// ---------------- xc @ W_xproj (K=256, N=40), BM=256, acc 8x5 -------------
__global__ __launch_bounds__(256) void xproj_kernel(
    const float* __restrict__ Ain, const float* __restrict__ W,
    float* __restrict__ outp)
{
    constexpr int BK = 32;
    __shared__ float As[256][36];   // row-major, pad 36 (aligned f4 stores)
    __shared__ float Bs[BK][40];
    const int tid = threadIdx.x;
    const int tx = tid & 7;      // 8 col groups * 5
    const int ty = tid >> 3;     // 32 row slots; rows = ty + 32*i
    const long rowBase = (long)blockIdx.x * 256;

    float acc[8][5];
#pragma unroll
    for (int i = 0; i < 8; i++)
#pragma unroll
        for (int j = 0; j < 5; j++) acc[i][j] = 0.f;

    for (int kt = 0; kt < 256; kt += BK) {
        // A tile: 256 rows x 32 k (2048 float4 loads, 8 per thread)
#pragma unroll
        for (int i = 0; i < 8; i++) {
            int lin = tid + i * 256;
            int r   = lin >> 3;
            int k4  = (lin & 7) * 4;
            float4 v = *reinterpret_cast<const float4*>(
                Ain + (rowBase + r) * 256 + kt + k4);
            *reinterpret_cast<float4*>(&As[r][k4]) = v;
        }
        // B tile: 32 x 40
#pragma unroll
        for (int i = 0; i < 5; i++) {
            int lin = tid + i * 256;
            int kr = lin / 40, c = lin % 40;
            Bs[kr][c] = W[(kt + kr) * 40 + c];
        }
        __syncthreads();
#pragma unroll
        for (int k = 0; k < BK; k++) {
            float b[5];
#pragma unroll
            for (int j = 0; j < 5; j++) b[j] = Bs[k][tx * 5 + j];
#pragma unroll
            for (int i = 0; i < 8; i++) {
                float a = As[ty + 32 * i][k];
#pragma unroll
                for (int j = 0; j < 5; j++) acc[i][j] += a * b[j];
            }
        }
        __syncthreads();
    }
#pragma unroll
    for (int i = 0; i < 8; i++) {
        long row = rowBase + ty + 32 * i;
#pragma unroll
        for (int j = 0; j < 5; j++) outp[row * 40 + tx * 5 + j] = acc[i][j];
    }
}

// ---------------- scan phase A (dt recomputed in-kernel) ------------------
__global__ __launch_bounds__(256) void scanA_kernel(
    const float* __restrict__ xcg, const float* __restrict__ dbl,
    const float* __restrict__ W_dt, const float* __restrict__ b_dt,
    const float* __restrict__ A_log,
    float* __restrict__ hloc, float* __restrict__ sumdtArr)
{
    const int bid = blockIdx.x;
    const int b = bid / NC, c = bid % NC;
    const long mbase = (long)b * L_ + (long)c * CL;
    const int d = threadIdx.x;

    float Ar[16]; bool fast = true;
#pragma unroll
    for (int s = 0; s < 16; s++) {
        Ar[s] = -__expf(A_log[d * 16 + s]);
        float n = (float)(s + 1);
        fast = fast && (fabsf(Ar[s] + n) < 1e-3f * n);
    }
    float wdt[8];
#pragma unroll
    for (int k = 0; k < 8; k++) wdt[k] = W_dt[k * 256 + d];
    const float bb = b_dt[d];

    __shared__ float sB[CL][16];
    __shared__ float sD[CL][8];
#pragma unroll
    for (int i = 0; i < 4; i++) {
        int lin = threadIdx.x + i * 256;
        sB[lin >> 4][lin & 15] = dbl[(mbase + (lin >> 4)) * 40 + 8 + (lin & 15)];
    }
#pragma unroll
    for (int i = 0; i < 2; i++) {
        int lin = threadIdx.x + i * 256;
        sD[lin >> 3][lin & 7] = dbl[(mbase + (lin >> 3)) * 40 + (lin & 7)];
    }
    __syncthreads();

    float h[16];
#pragma unroll
    for (int s = 0; s < 16; s++) h[s] = 0.f;
    float sumdt = 0.f;

    for (int t = 0; t < CL; t++) {
        long m = mbase + t;
        float pre = bb;
#pragma unroll
        for (int k = 0; k < 8; k++) pre += sD[t][k] * wdt[k];
        float e = __expf(pre);
        float dtv = (pre > 15.f) ? pre : __logf(1.f + e);
        float p = __fdividef(1.f, 1.f + e);       // exp(-softplus(pre))
        float xv = xcg[m * 256 + d];
        sumdt += dtv;
        float cc = dtv * xv;
        float pw[16];
        if (fast) {
            float p2 = p * p, p4 = p2 * p2, p8 = p4 * p4;
            pw[0] = p;        pw[1] = p2;       pw[2] = p2 * p;    pw[3] = p4;
            pw[4] = p4 * p;   pw[5] = p4 * p2;  pw[6] = p4 * pw[2];
            pw[7] = p8;       pw[8] = p8 * p;   pw[9] = p8 * p2;   pw[10] = p8 * pw[2];
            pw[11] = p8 * p4; pw[12] = p8 * pw[4]; pw[13] = p8 * pw[5];
            pw[14] = p8 * pw[6]; pw[15] = p8 * p8;
        } else {
#pragma unroll
            for (int s = 0; s < 16; s++) pw[s] = __expf(dtv * Ar[s]);
        }
#pragma unroll
        for (int s = 0; s < 16; s++) h[s] = pw[s] * h[s] + cc * sB[t][s];
    }

    long o = ((long)bid * 256 + d) * 16;
#pragma unroll
    for (int s = 0; s < 16; s += 4)
        *reinterpret_cast<float4*>(hloc + o + s) =
            make_float4(h[s], h[s + 1], h[s + 2], h[s + 3]);
    sumdtArr[(long)bid * 256 + d] = sumdt;
}

// ---------------- scan phase B ------------------------------------------
__global__ void scanB_kernel(const float* __restrict__ hloc,
                             const float* __restrict__ sumdtArr,
                             const float* __restrict__ A_log,
                             float* __restrict__ hin)
{
    int gid = blockIdx.x * 256 + threadIdx.x;
    int b = gid >> 12;
    int r = gid & 4095;
    int d = r >> 4, s = r & 15;
    float As_ = -__expf(A_log[d * 16 + s]);
    float h = 0.f;
    for (int c = 0; c < NC; c++) {
        long idx = ((long)(b * NC + c) * 256 + d);
        hin[idx * 16 + s] = h;
        float pw = __expf(As_ * sumdtArr[idx]);
        h = pw * h + hloc[idx * 16 + s];
    }
}

// ---------------- scan phase C: replay + gate, dt recomputed --------------
__global__ __launch_bounds__(256) void scanC_kernel(
    const float* __restrict__ xcg, const float* __restrict__ xz,
    const float* __restrict__ dbl,
    const float* __restrict__ W_dt, const float* __restrict__ b_dt,
    const float* __restrict__ A_log, const float* __restrict__ Dp,
    const float* __restrict__ hin,
    __half* __restrict__ yhi, __half* __restrict__ ylo)
{
    const int bid = blockIdx.x;
    const int b = bid / NC, c = bid % NC;
    const long mbase = (long)b * L_ + (long)c * CL;
    const int d = threadIdx.x;

    float Ar[16]; bool fast = true;
#pragma unroll
    for (int s = 0; s < 16; s++) {
        Ar[s] = -__expf(A_log[d * 16 + s]);
        float n = (float)(s + 1);
        fast = fast && (fabsf(Ar[s] + n) < 1e-3f * n);
    }
    float wdt[8];
#pragma unroll
    for (int k = 0; k < 8; k++) wdt[k] = W_dt[k * 256 + d];
    const float bb = b_dt[d];

    __shared__ float sB[CL][16];
    __shared__ float sC[CL][16];
    __shared__ float sD[CL][8];
#pragma unroll
    for (int i = 0; i < 4; i++) {
        int lin = threadIdx.x + i * 256;
        long mm = mbase + (lin >> 4);
        sB[lin >> 4][lin & 15] = dbl[mm * 40 + 8  + (lin & 15)];
        sC[lin >> 4][lin & 15] = dbl[mm * 40 + 24 + (lin & 15)];
    }
#pragma unroll
    for (int i = 0; i < 2; i++) {
        int lin = threadIdx.x + i * 256;
        sD[lin >> 3][lin & 7] = dbl[(mbase + (lin >> 3)) * 40 + (lin & 7)];
    }
    __syncthreads();

    float h[16];
    long o = ((long)bid * 256 + d) * 16;
#pragma unroll
    for (int s = 0; s < 16; s += 4) {
        float4 v = *reinterpret_cast<const float4*>(hin + o + s);
        h[s] = v.x; h[s + 1] = v.y; h[s + 2] = v.z; h[s + 3] = v.w;
    }
    const float Dd = Dp[d];

    for (int t = 0; t < CL; t++) {
        long m = mbase + t;
        float pre = bb;
#pragma unroll
        for (int k = 0; k < 8; k++) pre += sD[t][k] * wdt[k];
        float e = __expf(pre);
        float dtv = (pre > 15.f) ? pre : __logf(1.f + e);
        float p = __fdividef(1.f, 1.f + e);
        float xv = xcg[m * 256 + d];
        float cc = dtv * xv;
        float pw[16];
        if (fast) {
            float p2 = p * p, p4 = p2 * p2, p8 = p4 * p4;
            pw[0] = p;        pw[1] = p2;       pw[2] = p2 * p;    pw[3] = p4;
            pw[4] = p4 * p;   pw[5] = p4 * p2;  pw[6] = p4 * pw[2];
            pw[7] = p8;       pw[8] = p8 * p;   pw[9] = p8 * p2;   pw[10] = p8 * pw[2];
            pw[11] = p8 * p4; pw[12] = p8 * pw[4]; pw[13] = p8 * pw[5];
            pw[14] = p8 * pw[6]; pw[15] = p8 * p8;
        } else {
#pragma unroll
            for (int s = 0; s < 16; s++) pw[s] = __expf(dtv * Ar[s]);
        }
        float y = 0.f;
#pragma unroll
        for (int s = 0; s < 16; s++) {
            h[s] = pw[s] * h[s] + cc * sB[t][s];
            y += h[s] * sC[t][s];
        }
        float zv = xz[m * 512 + 256 + d];
        float sg = 1.f / (1.f + __expf(-zv));
        float v = (y + xv * Dd) * (zv * sg);
        __half hh = __float2half_rn(v);
        yhi[m * 256 + d] = hh;
        ylo[m * 256 + d] = __float2half_rn(v - __half2float(hh));
    }
}

// ---------------- launcher (stateless, call-invariant) --------------------
extern "C" void kernel_launch(void* const* d_in, const int* in_sizes, int n_in,
                              void* d_out, int out_size)
{
    const float* x      = (const float*)d_in[0];
    const float* qk     = (const float*)d_in[1];
    const float* W_mix  = (const float*)d_in[2];
    const float* b_mix  = (const float*)d_in[3];
    const float* W_in   = (const float*)d_in[4];
    const float* b_in   = (const float*)d_in[5];
    const float* conv_w = (const float*)d_in[6];
    const float* conv_b = (const float*)d_in[7];
    const float* W_xproj= (const float*)d_in[8];
    const float* W_dt   = (const float*)d_in[9];
    const float* b_dt   = (const float*)d_in[10];
    const float* A_log  = (const float*)d_in[11];
    const float* D_param= (const float*)d_in[12];
    const float* W_op   = (const float*)d_in[13];
    const float* b_op   = (const float*)d_in[14];
    const float* W_out  = (const float*)d_in[15];
    const float* b_out  = (const float*)d_in[16];
    float* out = (float*)d_out;

    float  *pxz, *pxc, *pdbl, *phloc, *phin, *psum;
    __half *phhi, *phlo, *pyhi, *pylo, *pt1hi, *pt1lo;
    __half *pwmixh, *pwmixl, *pwinh, *pwinl, *pwoph, *pwopl, *pwouth, *pwoutl;
    cudaGetSymbolAddress((void**)&pxz,   g_xz);
    cudaGetSymbolAddress((void**)&pxc,   g_xc);
    cudaGetSymbolAddress((void**)&pdbl,  g_dbl);
    cudaGetSymbolAddress((void**)&phloc, g_hloc);
    cudaGetSymbolAddress((void**)&phin,  g_hin);
    cudaGetSymbolAddress((void**)&psum,  g_sumdt);
    cudaGetSymbolAddress((void**)&phhi,  g_h_hi);
    cudaGetSymbolAddress((void**)&phlo,  g_h_lo);
    cudaGetSymbolAddress((void**)&pyhi,  g_yf_hi);
    cudaGetSymbolAddress((void**)&pylo,  g_yf_lo);
    cudaGetSymbolAddress((void**)&pt1hi, g_t1_hi);
    cudaGetSymbolAddress((void**)&pt1lo, g_t1_lo);
    cudaGetSymbolAddress((void**)&pwmixh, g_wmix_hi);
    cudaGetSymbolAddress((void**)&pwmixl, g_wmix_lo);
    cudaGetSymbolAddress((void**)&pwinh,  g_win_hi);
    cudaGetSymbolAddress((void**)&pwinl,  g_win_lo);
    cudaGetSymbolAddress((void**)&pwoph,  g_wop_hi);
    cudaGetSymbolAddress((void**)&pwopl,  g_wop_lo);
    cudaGetSymbolAddress((void**)&pwouth, g_wout_hi);
    cudaGetSymbolAddress((void**)&pwoutl, g_wout_lo);
    cudaFuncSetAttribute(tcgemm2<false, true>,
        cudaFuncAttributeMaxDynamicSharedMemorySize, GEMM_SMEM2);
    cudaFuncSetAttribute(tcgemm2<true, false>,
        cudaFuncAttributeMaxDynamicSharedMemorySize, GEMM_SMEM2);
    cudaFuncSetAttribute(tcgemm2<true, true>,
        cudaFuncAttributeMaxDynamicSharedMemorySize, GEMM_SMEM2);

    dim3 blk(256);
    // all four weight splits in one launch (196608 elements)
    split_all<<<768, 256>>>(W_mix, W_in, W_op, W_out,
                            pwmixh, pwmixl, pwinh, pwinl,
                            pwoph, pwopl, pwouth, pwoutl);

    // h = concat(x,qk) @ W_mix + b_mix  -> fp16 hi/lo   [65536,128], K=512
    tcgemm2<false, true><<<dim3(1, 512), blk, GEMM_SMEM2>>>(
        x, qk, 256, 256, 256, nullptr, nullptr,
        pwmixh, pwmixl, b_mix, nullptr, phhi, phlo, 128, 512);
    // xz = h @ W_in + b_in  -> fp32                      [65536,512], K=128
    tcgemm2<true, false><<<dim3(4, 512), blk, GEMM_SMEM2>>>(
        nullptr, nullptr, 0, 0, 0, phhi, phlo,
        pwinh, pwinl, b_in, pxz, nullptr, nullptr, 512, 128);
    // xc = silu(causal_conv(xz[:, :256])) — rolling window
    conv_silu_kernel<<<4096, 256>>>(pxz, conv_w, conv_b, pxc);
    // dbl = xc @ W_xproj                                  [65536,40]
    xproj_kernel<<<256, 256>>>(pxc, W_xproj, pdbl);
    // chunked selective scan (dt recomputed in-kernel from dbl)
    scanA_kernel<<<B_ * NC, 256>>>(pxc, pdbl, W_dt, b_dt, A_log, phloc, psum);
    scanB_kernel<<<256, 256>>>(phloc, psum, A_log, phin);
    scanC_kernel<<<B_ * NC, 256>>>(pxc, pxz, pdbl, W_dt, b_dt, A_log, D_param,
                                   phin, pyhi, pylo);
    // t1 = yf @ W_op + b_op  -> fp16 hi/lo                [65536,128], K=256
    tcgemm2<true, true><<<dim3(1, 512), blk, GEMM_SMEM2>>>(
        nullptr, nullptr, 0, 0, 0, pyhi, pylo,
        pwoph, pwopl, b_op, nullptr, pt1hi, pt1lo, 128, 256);
    // out = t1 @ W_out + b_out -> fp32                    [65536,256], K=128
    tcgemm2<true, false><<<dim3(2, 512), blk, GEMM_SMEM2>>>(
        nullptr, nullptr, 0, 0, 0, pt1hi, pt1lo,
        pwouth, pwoutl, b_out, out, nullptr, nullptr, 256, 128);
}

// round 14
// speedup vs baseline: 1.1841x; 1.0169x over previous
#include <cuda_runtime.h>
#include <cuda_fp16.h>
#include <math.h>
#include <stdint.h>

// Problem constants
constexpr int B_  = 16;
constexpr int L_  = 4096;
constexpr int DI  = 256;   // D_INNER
constexpr int DS  = 16;    // D_STATE
constexpr long BLD = (long)B_ * L_;   // 65536 tokens

constexpr int CL  = 64;          // chunk length for scan
constexpr int NC  = L_ / CL;     // 64 chunks

// ---------------- scratch (device globals; no allocation) ----------------
__device__ float  g_xz  [BLD * 512];      // after W_in (xc_raw | z)
__device__ float  g_xc  [BLD * DI];       // after conv+silu
__device__ float  g_dbl [BLD * 40];       // xproj output (dtrank|B|C)
__device__ float  g_hloc[(long)B_ * NC * DI * DS];
__device__ float  g_hin [(long)B_ * NC * DI * DS];
__device__ float  g_sumdt[(long)B_ * NC * DI];
// fp16 hi/lo activation carries
__device__ __half g_h_hi [BLD * 128];
__device__ __half g_h_lo [BLD * 128];
__device__ __half g_yf_hi[BLD * 256];
__device__ __half g_yf_lo[BLD * 256];
// fp16 hi/lo weights
__device__ __half g_wmix_hi[512 * 128], g_wmix_lo[512 * 128];
__device__ __half g_win_hi [128 * 512], g_win_lo [128 * 512];
__device__ __half g_wcomb_hi[256 * 256], g_wcomb_lo[256 * 256];
__device__ float  g_bcomb[256];

// ======================= helpers =========================================
__device__ __forceinline__ uint32_t smem_u32(const void* p) {
    uint32_t a;
    asm("{ .reg .u64 t; cvta.to.shared.u64 t, %1; cvt.u32.u64 %0, t; }"
        : "=r"(a) : "l"(p));
    return a;
}
__device__ __forceinline__ void cpa16(uint32_t dst, const void* src) {
    asm volatile("cp.async.cg.shared.global [%0], [%1], 16;"
                 :: "r"(dst), "l"(src) : "memory");
}
__device__ __forceinline__ void cpa_commit() {
    asm volatile("cp.async.commit_group;" ::: "memory");
}
__device__ __forceinline__ void cpa_wait0() {
    asm volatile("cp.async.wait_group 0;" ::: "memory");
}
__device__ __forceinline__ void ldsm_x4(uint32_t* r, uint32_t addr) {
    asm volatile("ldmatrix.sync.aligned.m8n8.x4.shared.b16 {%0,%1,%2,%3}, [%4];"
        : "=r"(r[0]), "=r"(r[1]), "=r"(r[2]), "=r"(r[3]) : "r"(addr));
}
__device__ __forceinline__ void ldsm_x4_t(uint32_t* r, uint32_t addr) {
    asm volatile("ldmatrix.sync.aligned.m8n8.x4.trans.shared.b16 {%0,%1,%2,%3}, [%4];"
        : "=r"(r[0]), "=r"(r[1]), "=r"(r[2]), "=r"(r[3]) : "r"(addr));
}
__device__ __forceinline__ void mma16816(float* c, const uint32_t* a,
                                         uint32_t b0, uint32_t b1) {
    asm volatile("mma.sync.aligned.m16n8k16.row.col.f32.f16.f16.f32 "
        "{%0,%1,%2,%3}, {%4,%5,%6,%7}, {%8,%9}, {%0,%1,%2,%3};"
        : "+f"(c[0]), "+f"(c[1]), "+f"(c[2]), "+f"(c[3])
        : "r"(a[0]), "r"(a[1]), "r"(a[2]), "r"(a[3]), "r"(b0), "r"(b1));
}

// ---------------- weight splitter (Wmix + Win) ----------------------------
__global__ void split_all(const float* __restrict__ Wmix,
                          const float* __restrict__ Win,
                          __half* __restrict__ mh, __half* __restrict__ ml,
                          __half* __restrict__ ih, __half* __restrict__ il)
{
    int i = blockIdx.x * 256 + threadIdx.x;   // 0..131071
    const float* src; __half *dh, *dl; int j;
    if (i < 65536) { src = Wmix; dh = mh; dl = ml; j = i; }
    else           { src = Win;  dh = ih; dl = il; j = i - 65536; }
    float v = src[j];
    __half h = __float2half_rn(v);
    dh[j] = h;
    dl[j] = __float2half_rn(v - __half2float(h));
}

// ---------------- W_comb = W_op @ W_out (+ b_comb), hi/lo output ----------
__global__ __launch_bounds__(256) void combine_w(
    const float* __restrict__ Wop, const float* __restrict__ Wout,
    const float* __restrict__ bop, const float* __restrict__ bout,
    __half* __restrict__ ch, __half* __restrict__ cl, float* __restrict__ bc)
{
    __shared__ float row[128];
    const int i = blockIdx.x, j = threadIdx.x;
    if (j < 128) row[j] = Wop[i * 128 + j];
    __syncthreads();
    float acc = 0.f;
    for (int k = 0; k < 128; k++) acc += row[k] * Wout[k * 256 + j];
    __half h = __float2half_rn(acc);
    ch[i * 256 + j] = h;
    cl[i * 256 + j] = __float2half_rn(acc - __half2float(h));
    if (i == 0) {
        float b = bout[j];
        for (int k = 0; k < 128; k++) b += bop[k] * Wout[k * 256 + j];
        bc[j] = b;
    }
}

// ====== tensor-core GEMM (mma.sync, fp16 hi/lo, compact smem) ============
constexpr int SAW2 = 72;
constexpr int SBW  = 136;
constexpr int SMEM_A2 = 128 * SAW2 * 2;    // 18432
constexpr int SMEM_B2 = 64 * SBW * 2;      // 17408
constexpr int SM_STAGE2 = SMEM_A2 + SMEM_B2;   // 35840
constexpr int GEMM_SMEM2 = 2 * SM_STAGE2;      // 71680

template<bool ASPLIT, bool OSPLIT>
__global__ __launch_bounds__(256) void tcgemm2(
    const float* __restrict__ A0f, const float* __restrict__ A1f,
    int K0, int sA0, int sA1,
    const __half* __restrict__ Ahi, const __half* __restrict__ Alo,
    const __half* __restrict__ Whi, const __half* __restrict__ Wlo,
    const float* __restrict__ bias,
    float* __restrict__ Cf, __half* __restrict__ Chi, __half* __restrict__ Clo,
    int N, int K)
{
    extern __shared__ char smem[];
    const int tid = threadIdx.x;
    const int wid = tid >> 5, lane = tid & 31;
    const int wm = wid & 3, wn = wid >> 2;
    const long rowBase = (long)blockIdx.y * 128;
    const int  colBase = blockIdx.x * 128;

    float acc[2][8][4];
#pragma unroll
    for (int i = 0; i < 2; i++)
#pragma unroll
        for (int j = 0; j < 8; j++)
#pragma unroll
            for (int e = 0; e < 4; e++) acc[i][j][e] = 0.f;

    const uint32_t sb0 = smem_u32(smem);
    uint32_t aAddr[2], bAddr[4];
#pragma unroll
    for (int mf = 0; mf < 2; mf++)
        aAddr[mf] = sb0 + (uint32_t)(((wm * 32 + mf * 16 + (lane & 15)) * SAW2
                                      + (lane >> 4) * 8) * 2);
#pragma unroll
    for (int ng = 0; ng < 4; ng++)
        bAddr[ng] = sb0 + SMEM_A2 + (uint32_t)(((lane & 15) * SBW
                                      + wn * 64 + ng * 16 + (lane >> 4) * 8) * 2);

    const int nch = K / 32;

    auto loadTiles = [&](int ch, int st) {
        const int kt = ch * 32;
        const uint32_t sbA = sb0 + st * SM_STAGE2;
        const uint32_t sbB = sbA + SMEM_A2;
#pragma unroll
        for (int i = 0; i < 4; i++) {
            int lin = tid + i * 256;
            int row = lin >> 4, u = lin & 15;
            const __half* src = ((row >= 32) ? Wlo : Whi)
                + (long)(kt + (row & 31)) * N + colBase + u * 8;
            cpa16(sbB + (uint32_t)(row * SBW + u * 8) * 2, src);
        }
        if (ASPLIT) {
            const int r = tid >> 1, q = tid & 1;
            const __half* sh = Ahi + (rowBase + r) * (long)K + kt + q * 16;
            const __half* sl = Alo + (rowBase + r) * (long)K + kt + q * 16;
            uint32_t dh = sbA + (uint32_t)(r * SAW2 + q * 16) * 2;
            uint32_t dl = sbA + (uint32_t)(r * SAW2 + 32 + q * 16) * 2;
            cpa16(dh, sh);      cpa16(dh + 16, sh + 8);
            cpa16(dl, sl);      cpa16(dl + 16, sl + 8);
        } else {
            const float* Ap; int sA_, kof;
            if (kt < K0) { Ap = A0f; sA_ = sA0; kof = kt; }
            else         { Ap = A1f; sA_ = sA1; kof = kt - K0; }
            const int r = tid >> 1, q = tid & 1;
            const float4* src = reinterpret_cast<const float4*>(
                Ap + (rowBase + r) * (long)sA_ + kof + q * 16);
            __half* rowp = reinterpret_cast<__half*>(smem + st * SM_STAGE2)
                           + r * SAW2;
#pragma unroll
            for (int j = 0; j < 4; j++) {
                float4 v = src[j];
                int c = q * 16 + j * 4;
                __half hx = __float2half_rn(v.x), hy = __float2half_rn(v.y);
                __half hz = __float2half_rn(v.z), hw = __float2half_rn(v.w);
                __half lx = __float2half_rn(v.x - __half2float(hx));
                __half ly = __float2half_rn(v.y - __half2float(hy));
                __half lz = __float2half_rn(v.z - __half2float(hz));
                __half lw = __float2half_rn(v.w - __half2float(hw));
                __half2 h01 = __halves2half2(hx, hy), h23 = __halves2half2(hz, hw);
                __half2 l01 = __halves2half2(lx, ly), l23 = __halves2half2(lz, lw);
                *reinterpret_cast<uint2*>(rowp + c) =
                    make_uint2(*(uint32_t*)&h01, *(uint32_t*)&h23);
                *reinterpret_cast<uint2*>(rowp + 32 + c) =
                    make_uint2(*(uint32_t*)&l01, *(uint32_t*)&l23);
            }
        }
    };

    loadTiles(0, 0);
    cpa_commit();

    for (int ch = 0; ch < nch; ch++) {
        cpa_wait0();
        __syncthreads();
        if (ch + 1 < nch) { loadTiles(ch + 1, (ch + 1) & 1); cpa_commit(); }

        const uint32_t so = (uint32_t)((ch & 1) * SM_STAGE2);
        const int aof[6] = {0, 16, 32, 48, 0, 16};
        const int bof[6] = {0, 16, 0, 16, 32, 48};
#pragma unroll
        for (int s = 0; s < 6; s++) {
            uint32_t afr[2][4];
            ldsm_x4(afr[0], aAddr[0] + so + aof[s] * 2);
            ldsm_x4(afr[1], aAddr[1] + so + aof[s] * 2);
            uint32_t bfr[4][4];
#pragma unroll
            for (int ng = 0; ng < 4; ng++)
                ldsm_x4_t(bfr[ng], bAddr[ng] + so + bof[s] * SBW * 2);
#pragma unroll
            for (int ng = 0; ng < 4; ng++) {
#pragma unroll
                for (int mf = 0; mf < 2; mf++) {
                    mma16816(acc[mf][ng * 2],     afr[mf], bfr[ng][0], bfr[ng][1]);
                    mma16816(acc[mf][ng * 2 + 1], afr[mf], bfr[ng][2], bfr[ng][3]);
                }
            }
        }
    }

    // ---- epilogue ----
#pragma unroll
    for (int mf = 0; mf < 2; mf++) {
        long row = rowBase + wm * 32 + mf * 16 + (lane >> 2);
#pragma unroll
        for (int nf = 0; nf < 8; nf++) {
            int col = colBase + wn * 64 + nf * 8 + (lane & 3) * 2;
            float bx = bias[col], by = bias[col + 1];
            float v0 = acc[mf][nf][0] + bx, v1 = acc[mf][nf][1] + by;
            float v2 = acc[mf][nf][2] + bx, v3 = acc[mf][nf][3] + by;
            if (OSPLIT) {
                __half h0 = __float2half_rn(v0), h1 = __float2half_rn(v1);
                __half h2 = __float2half_rn(v2), h3 = __float2half_rn(v3);
                __half2 hi0 = __halves2half2(h0, h1), hi1 = __halves2half2(h2, h3);
                __half2 lo0 = __halves2half2(
                    __float2half_rn(v0 - __half2float(h0)),
                    __float2half_rn(v1 - __half2float(h1)));
                __half2 lo1 = __halves2half2(
                    __float2half_rn(v2 - __half2float(h2)),
                    __float2half_rn(v3 - __half2float(h3)));
                *reinterpret_cast<__half2*>(Chi + row * (long)N + col) = hi0;
                *reinterpret_cast<__half2*>(Clo + row * (long)N + col) = lo0;
                *reinterpret_cast<__half2*>(Chi + (row + 8) * (long)N + col) = hi1;
                *reinterpret_cast<__half2*>(Clo + (row + 8) * (long)N + col) = lo1;
            } else {
                *reinterpret_cast<float2*>(Cf + row * (long)N + col) =
                    make_float2(v0, v1);
                *reinterpret_cast<float2*>(Cf + (row + 8) * (long)N + col) =
                    make_float2(v2, v3);
            }
        }
    }
}

// ---------------- depthwise causal conv + SiLU, rolling window ------------
__global__ void conv_silu_kernel(const float* __restrict__ xz,
                                 const float* __restrict__ cw,
                                 const float* __restrict__ cb,
                                 float* __restrict__ xc)
{
    int gid = blockIdx.x * 256 + threadIdx.x;   // 0 .. 1048575
    int d = gid & 255;
    long tb = (long)(gid >> 8) * 16;            // token base
    int l = (int)(tb & (L_ - 1));

    const float w0 = cw[d * 4 + 0], w1 = cw[d * 4 + 1];
    const float w2 = cw[d * 4 + 2], w3 = cw[d * 4 + 3];
    const float cbd = cb[d];

    float x3 = 0.f, x2 = 0.f, x1 = 0.f;
    if (l > 0) {
        x3 = xz[(tb - 3) * 512 + d];
        x2 = xz[(tb - 2) * 512 + d];
        x1 = xz[(tb - 1) * 512 + d];
    }
#pragma unroll
    for (int t = 0; t < 16; t++) {
        float xt = xz[(tb + t) * 512 + d];
        float a = cbd + w0 * x3 + w1 * x2 + w2 * x1 + w3 * xt;
        float s = 1.f / (1.f + __expf(-a));
        xc[(tb + t) * 256 + d] = a * s;
        x3 = x2; x2 = x1; x1 = xt;
    }
}

// ---------------- xc @ W_xproj (K=256, N=40), BM=256, acc 8x5 -------------
__global__ __launch_bounds__(256) void xproj_kernel(
    const float* __restrict__ Ain, const float* __restrict__ W,
    float* __restrict__ outp)
{
    constexpr int BK = 32;
    __shared__ float As[256][36];
    __shared__ float Bs[BK][40];
    const int tid = threadIdx.x;
    const int tx = tid & 7;
    const int ty = tid >> 3;
    const long rowBase = (long)blockIdx.x * 256;

    float acc[8][5];
#pragma unroll
    for (int i = 0; i < 8; i++)
#pragma unroll
        for (int j = 0; j < 5; j++) acc[i][j] = 0.f;

    for (int kt = 0; kt < 256; kt += BK) {
#pragma unroll
        for (int i = 0; i < 8; i++) {
            int lin = tid + i * 256;
            int r   = lin >> 3;
            int k4  = (lin & 7) * 4;
            float4 v = *reinterpret_cast<const float4*>(
                Ain + (rowBase + r) * 256 + kt + k4);
            *reinterpret_cast<float4*>(&As[r][k4]) = v;
        }
#pragma unroll
        for (int i = 0; i < 5; i++) {
            int lin = tid + i * 256;
            int kr = lin / 40, c = lin % 40;
            Bs[kr][c] = W[(kt + kr) * 40 + c];
        }
        __syncthreads();
#pragma unroll
        for (int k = 0; k < BK; k++) {
            float b[5];
#pragma unroll
            for (int j = 0; j < 5; j++) b[j] = Bs[k][tx * 5 + j];
#pragma unroll
            for (int i = 0; i < 8; i++) {
                float a = As[ty + 32 * i][k];
#pragma unroll
                for (int j = 0; j < 5; j++) acc[i][j] += a * b[j];
            }
        }
        __syncthreads();
    }
#pragma unroll
    for (int i = 0; i < 8; i++) {
        long row = rowBase + ty + 32 * i;
#pragma unroll
        for (int j = 0; j < 5; j++) outp[row * 40 + tx * 5 + j] = acc[i][j];
    }
}

// ---------------- scan phase A (dt recomputed in-kernel) ------------------
__global__ __launch_bounds__(256) void scanA_kernel(
    const float* __restrict__ xcg, const float* __restrict__ dbl,
    const float* __restrict__ W_dt, const float* __restrict__ b_dt,
    const float* __restrict__ A_log,
    float* __restrict__ hloc, float* __restrict__ sumdtArr)
{
    const int bid = blockIdx.x;
    const int b = bid / NC, c = bid % NC;
    const long mbase = (long)b * L_ + (long)c * CL;
    const int d = threadIdx.x;

    float Ar[16]; bool fast = true;
#pragma unroll
    for (int s = 0; s < 16; s++) {
        Ar[s] = -__expf(A_log[d * 16 + s]);
        float n = (float)(s + 1);
        fast = fast && (fabsf(Ar[s] + n) < 1e-3f * n);
    }
    float wdt[8];
#pragma unroll
    for (int k = 0; k < 8; k++) wdt[k] = W_dt[k * 256 + d];
    const float bb = b_dt[d];

    __shared__ float sB[CL][16];
    __shared__ float sD[CL][8];
#pragma unroll
    for (int i = 0; i < 4; i++) {
        int lin = threadIdx.x + i * 256;
        sB[lin >> 4][lin & 15] = dbl[(mbase + (lin >> 4)) * 40 + 8 + (lin & 15)];
    }
#pragma unroll
    for (int i = 0; i < 2; i++) {
        int lin = threadIdx.x + i * 256;
        sD[lin >> 3][lin & 7] = dbl[(mbase + (lin >> 3)) * 40 + (lin & 7)];
    }
    __syncthreads();

    float h[16];
#pragma unroll
    for (int s = 0; s < 16; s++) h[s] = 0.f;
    float sumdt = 0.f;

    for (int t = 0; t < CL; t++) {
        long m = mbase + t;
        float pre = bb;
#pragma unroll
        for (int k = 0; k < 8; k++) pre += sD[t][k] * wdt[k];
        float e = __expf(pre);
        float dtv = (pre > 15.f) ? pre : __logf(1.f + e);
        float p = __fdividef(1.f, 1.f + e);       // exp(-softplus(pre))
        float xv = xcg[m * 256 + d];
        sumdt += dtv;
        float cc = dtv * xv;
        float pw[16];
        if (fast) {
            float p2 = p * p, p4 = p2 * p2, p8 = p4 * p4;
            pw[0] = p;        pw[1] = p2;       pw[2] = p2 * p;    pw[3] = p4;
            pw[4] = p4 * p;   pw[5] = p4 * p2;  pw[6] = p4 * pw[2];
            pw[7] = p8;       pw[8] = p8 * p;   pw[9] = p8 * p2;   pw[10] = p8 * pw[2];
            pw[11] = p8 * p4; pw[12] = p8 * pw[4]; pw[13] = p8 * pw[5];
            pw[14] = p8 * pw[6]; pw[15] = p8 * p8;
        } else {
#pragma unroll
            for (int s = 0; s < 16; s++) pw[s] = __expf(dtv * Ar[s]);
        }
#pragma unroll
        for (int s = 0; s < 16; s++) h[s] = pw[s] * h[s] + cc * sB[t][s];
    }

    long o = ((long)bid * 256 + d) * 16;
#pragma unroll
    for (int s = 0; s < 16; s += 4)
        *reinterpret_cast<float4*>(hloc + o + s) =
            make_float4(h[s], h[s + 1], h[s + 2], h[s + 3]);
    sumdtArr[(long)bid * 256 + d] = sumdt;
}

// ---------------- scan phase B ------------------------------------------
__global__ void scanB_kernel(const float* __restrict__ hloc,
                             const float* __restrict__ sumdtArr,
                             const float* __restrict__ A_log,
                             float* __restrict__ hin)
{
    int gid = blockIdx.x * 256 + threadIdx.x;
    int b = gid >> 12;
    int r = gid & 4095;
    int d = r >> 4, s = r & 15;
    float As_ = -__expf(A_log[d * 16 + s]);
    float h = 0.f;
    for (int c = 0; c < NC; c++) {
        long idx = ((long)(b * NC + c) * 256 + d);
        hin[idx * 16 + s] = h;
        float pw = __expf(As_ * sumdtArr[idx]);
        h = pw * h + hloc[idx * 16 + s];
    }
}

// ---------------- scan phase C: replay + gate, dt recomputed --------------
__global__ __launch_bounds__(256) void scanC_kernel(
    const float* __restrict__ xcg, const float* __restrict__ xz,
    const float* __restrict__ dbl,
    const float* __restrict__ W_dt, const float* __restrict__ b_dt,
    const float* __restrict__ A_log, const float* __restrict__ Dp,
    const float* __restrict__ hin,
    __half* __restrict__ yhi, __half* __restrict__ ylo)
{
    const int bid = blockIdx.x;
    const int b = bid / NC, c = bid % NC;
    const long mbase = (long)b * L_ + (long)c * CL;
    const int d = threadIdx.x;

    float Ar[16]; bool fast = true;
#pragma unroll
    for (int s = 0; s < 16; s++) {
        Ar[s] = -__expf(A_log[d * 16 + s]);
        float n = (float)(s + 1);
        fast = fast && (fabsf(Ar[s] + n) < 1e-3f * n);
    }
    float wdt[8];
#pragma unroll
    for (int k = 0; k < 8; k++) wdt[k] = W_dt[k * 256 + d];
    const float bb = b_dt[d];

    __shared__ float sB[CL][16];
    __shared__ float sC[CL][16];
    __shared__ float sD[CL][8];
#pragma unroll
    for (int i = 0; i < 4; i++) {
        int lin = threadIdx.x + i * 256;
        long mm = mbase + (lin >> 4);
        sB[lin >> 4][lin & 15] = dbl[mm * 40 + 8  + (lin & 15)];
        sC[lin >> 4][lin & 15] = dbl[mm * 40 + 24 + (lin & 15)];
    }
#pragma unroll
    for (int i = 0; i < 2; i++) {
        int lin = threadIdx.x + i * 256;
        sD[lin >> 3][lin & 7] = dbl[(mbase + (lin >> 3)) * 40 + (lin & 7)];
    }
    __syncthreads();

    float h[16];
    long o = ((long)bid * 256 + d) * 16;
#pragma unroll
    for (int s = 0; s < 16; s += 4) {
        float4 v = *reinterpret_cast<const float4*>(hin + o + s);
        h[s] = v.x; h[s + 1] = v.y; h[s + 2] = v.z; h[s + 3] = v.w;
    }
    const float Dd = Dp[d];

    for (int t = 0; t < CL; t++) {
        long m = mbase + t;
        float pre = bb;
#pragma unroll
        for (int k = 0; k < 8; k++) pre += sD[t][k] * wdt[k];
        float e = __expf(pre);
        float dtv = (pre > 15.f) ? pre : __logf(1.f + e);
        float p = __fdividef(1.f, 1.f + e);
        float xv = xcg[m * 256 + d];
        float cc = dtv * xv;
        float pw[16];
        if (fast) {
            float p2 = p * p, p4 = p2 * p2, p8 = p4 * p4;
            pw[0] = p;        pw[1] = p2;       pw[2] = p2 * p;    pw[3] = p4;
            pw[4] = p4 * p;   pw[5] = p4 * p2;  pw[6] = p4 * pw[2];
            pw[7] = p8;       pw[8] = p8 * p;   pw[9] = p8 * p2;   pw[10] = p8 * pw[2];
            pw[11] = p8 * p4; pw[12] = p8 * pw[4]; pw[13] = p8 * pw[5];
            pw[14] = p8 * pw[6]; pw[15] = p8 * p8;
        } else {
#pragma unroll
            for (int s = 0; s < 16; s++) pw[s] = __expf(dtv * Ar[s]);
        }
        float y = 0.f;
#pragma unroll
        for (int s = 0; s < 16; s++) {
            h[s] = pw[s] * h[s] + cc * sB[t][s];
            y += h[s] * sC[t][s];
        }
        float zv = xz[m * 512 + 256 + d];
        float sg = 1.f / (1.f + __expf(-zv));
        float v = (y + xv * Dd) * (zv * sg);
        __half hh = __float2half_rn(v);
        yhi[m * 256 + d] = hh;
        ylo[m * 256 + d] = __float2half_rn(v - __half2float(hh));
    }
}

// ---------------- launcher (stateless, call-invariant) --------------------
extern "C" void kernel_launch(void* const* d_in, const int* in_sizes, int n_in,
                              void* d_out, int out_size)
{
    const float* x      = (const float*)d_in[0];
    const float* qk     = (const float*)d_in[1];
    const float* W_mix  = (const float*)d_in[2];
    const float* b_mix  = (const float*)d_in[3];
    const float* W_in   = (const float*)d_in[4];
    const float* b_in   = (const float*)d_in[5];
    const float* conv_w = (const float*)d_in[6];
    const float* conv_b = (const float*)d_in[7];
    const float* W_xproj= (const float*)d_in[8];
    const float* W_dt   = (const float*)d_in[9];
    const float* b_dt   = (const float*)d_in[10];
    const float* A_log  = (const float*)d_in[11];
    const float* D_param= (const float*)d_in[12];
    const float* W_op   = (const float*)d_in[13];
    const float* b_op   = (const float*)d_in[14];
    const float* W_out  = (const float*)d_in[15];
    const float* b_out  = (const float*)d_in[16];
    float* out = (float*)d_out;

    float  *pxz, *pxc, *pdbl, *phloc, *phin, *psum, *pbcomb;
    __half *phhi, *phlo, *pyhi, *pylo;
    __half *pwmixh, *pwmixl, *pwinh, *pwinl, *pwch, *pwcl;
    cudaGetSymbolAddress((void**)&pxz,   g_xz);
    cudaGetSymbolAddress((void**)&pxc,   g_xc);
    cudaGetSymbolAddress((void**)&pdbl,  g_dbl);
    cudaGetSymbolAddress((void**)&phloc, g_hloc);
    cudaGetSymbolAddress((void**)&phin,  g_hin);
    cudaGetSymbolAddress((void**)&psum,  g_sumdt);
    cudaGetSymbolAddress((void**)&phhi,  g_h_hi);
    cudaGetSymbolAddress((void**)&phlo,  g_h_lo);
    cudaGetSymbolAddress((void**)&pyhi,  g_yf_hi);
    cudaGetSymbolAddress((void**)&pylo,  g_yf_lo);
    cudaGetSymbolAddress((void**)&pwmixh, g_wmix_hi);
    cudaGetSymbolAddress((void**)&pwmixl, g_wmix_lo);
    cudaGetSymbolAddress((void**)&pwinh,  g_win_hi);
    cudaGetSymbolAddress((void**)&pwinl,  g_win_lo);
    cudaGetSymbolAddress((void**)&pwch,   g_wcomb_hi);
    cudaGetSymbolAddress((void**)&pwcl,   g_wcomb_lo);
    cudaGetSymbolAddress((void**)&pbcomb, g_bcomb);
    cudaFuncSetAttribute(tcgemm2<false, true>,
        cudaFuncAttributeMaxDynamicSharedMemorySize, GEMM_SMEM2);
    cudaFuncSetAttribute(tcgemm2<true, false>,
        cudaFuncAttributeMaxDynamicSharedMemorySize, GEMM_SMEM2);
    cudaFuncSetAttribute(tcgemm2<true, true>,
        cudaFuncAttributeMaxDynamicSharedMemorySize, GEMM_SMEM2);

    dim3 blk(256);
    // weight prep: split Wmix/Win; combine W_op@W_out -> hi/lo + b_comb
    split_all<<<512, 256>>>(W_mix, W_in, pwmixh, pwmixl, pwinh, pwinl);
    combine_w<<<256, 256>>>(W_op, W_out, b_op, b_out, pwch, pwcl, pbcomb);

    // h = concat(x,qk) @ W_mix + b_mix  -> fp16 hi/lo   [65536,128], K=512
    tcgemm2<false, true><<<dim3(1, 512), blk, GEMM_SMEM2>>>(
        x, qk, 256, 256, 256, nullptr, nullptr,
        pwmixh, pwmixl, b_mix, nullptr, phhi, phlo, 128, 512);
    // xz = h @ W_in + b_in  -> fp32                      [65536,512], K=128
    tcgemm2<true, false><<<dim3(4, 512), blk, GEMM_SMEM2>>>(
        nullptr, nullptr, 0, 0, 0, phhi, phlo,
        pwinh, pwinl, b_in, pxz, nullptr, nullptr, 512, 128);
    // xc = silu(causal_conv(xz[:, :256])) — rolling window
    conv_silu_kernel<<<4096, 256>>>(pxz, conv_w, conv_b, pxc);
    // dbl = xc @ W_xproj                                  [65536,40]
    xproj_kernel<<<256, 256>>>(pxc, W_xproj, pdbl);
    // chunked selective scan (dt recomputed in-kernel from dbl)
    scanA_kernel<<<B_ * NC, 256>>>(pxc, pdbl, W_dt, b_dt, A_log, phloc, psum);
    scanB_kernel<<<256, 256>>>(phloc, psum, A_log, phin);
    scanC_kernel<<<B_ * NC, 256>>>(pxc, pxz, pdbl, W_dt, b_dt, A_log, D_param,
                                   phin, pyhi, pylo);
    // out = yf @ (W_op@W_out) + b_comb  -> fp32           [65536,256], K=256
    tcgemm2<true, false><<<dim3(2, 512), blk, GEMM_SMEM2>>>(
        nullptr, nullptr, 0, 0, 0, pyhi, pylo,
        pwch, pwcl, pbcomb, out, nullptr, nullptr, 256, 256);
}

// round 15
// speedup vs baseline: 1.2633x; 1.0669x over previous
#include <cuda_runtime.h>
#include <cuda_fp16.h>
#include <math.h>
#include <stdint.h>

// Problem constants
constexpr int B_  = 16;
constexpr int L_  = 4096;
constexpr int DI  = 256;   // D_INNER
constexpr int DS  = 16;    // D_STATE
constexpr long BLD = (long)B_ * L_;   // 65536 tokens

constexpr int CL  = 64;          // chunk length for scan
constexpr int NC  = L_ / CL;     // 64 chunks

// ---------------- scratch (device globals; no allocation) ----------------
__device__ float  g_xz  [BLD * 512];      // after W_in (xc_raw | z)
__device__ float  g_xc  [BLD * DI];       // after conv+silu
__device__ float  g_dbl [BLD * 40];       // xproj output (dtrank|B|C)
__device__ float  g_hloc[(long)B_ * NC * DI * DS];
__device__ float  g_hin [(long)B_ * NC * DI * DS];
__device__ float  g_sumdt[(long)B_ * NC * DI];
// fp16 hi/lo activation carries
__device__ __half g_h_hi [BLD * 128];
__device__ __half g_h_lo [BLD * 128];
__device__ __half g_yf_hi[BLD * 256];
__device__ __half g_yf_lo[BLD * 256];
// fp16 hi/lo weights
__device__ __half g_wmix_hi[512 * 128], g_wmix_lo[512 * 128];
__device__ __half g_win_hi [128 * 512], g_win_lo [128 * 512];
__device__ __half g_wcomb_hi[256 * 256], g_wcomb_lo[256 * 256];
__device__ float  g_bcomb[256];

// ======================= helpers =========================================
__device__ __forceinline__ uint32_t smem_u32(const void* p) {
    uint32_t a;
    asm("{ .reg .u64 t; cvta.to.shared.u64 t, %1; cvt.u32.u64 %0, t; }"
        : "=r"(a) : "l"(p));
    return a;
}
__device__ __forceinline__ void cpa16(uint32_t dst, const void* src) {
    asm volatile("cp.async.cg.shared.global [%0], [%1], 16;"
                 :: "r"(dst), "l"(src) : "memory");
}
__device__ __forceinline__ void cpa_commit() {
    asm volatile("cp.async.commit_group;" ::: "memory");
}
__device__ __forceinline__ void cpa_wait0() {
    asm volatile("cp.async.wait_group 0;" ::: "memory");
}
__device__ __forceinline__ void ldsm_x4(uint32_t* r, uint32_t addr) {
    asm volatile("ldmatrix.sync.aligned.m8n8.x4.shared.b16 {%0,%1,%2,%3}, [%4];"
        : "=r"(r[0]), "=r"(r[1]), "=r"(r[2]), "=r"(r[3]) : "r"(addr));
}
__device__ __forceinline__ void ldsm_x4_t(uint32_t* r, uint32_t addr) {
    asm volatile("ldmatrix.sync.aligned.m8n8.x4.trans.shared.b16 {%0,%1,%2,%3}, [%4];"
        : "=r"(r[0]), "=r"(r[1]), "=r"(r[2]), "=r"(r[3]) : "r"(addr));
}
__device__ __forceinline__ void mma16816(float* c, const uint32_t* a,
                                         uint32_t b0, uint32_t b1) {
    asm volatile("mma.sync.aligned.m16n8k16.row.col.f32.f16.f16.f32 "
        "{%0,%1,%2,%3}, {%4,%5,%6,%7}, {%8,%9}, {%0,%1,%2,%3};"
        : "+f"(c[0]), "+f"(c[1]), "+f"(c[2]), "+f"(c[3])
        : "r"(a[0]), "r"(a[1]), "r"(a[2]), "r"(a[3]), "r"(b0), "r"(b1));
}

// ---------------- weight splitter (Wmix + Win) ----------------------------
__global__ void split_all(const float* __restrict__ Wmix,
                          const float* __restrict__ Win,
                          __half* __restrict__ mh, __half* __restrict__ ml,
                          __half* __restrict__ ih, __half* __restrict__ il)
{
    int i = blockIdx.x * 256 + threadIdx.x;   // 0..131071
    const float* src; __half *dh, *dl; int j;
    if (i < 65536) { src = Wmix; dh = mh; dl = ml; j = i; }
    else           { src = Win;  dh = ih; dl = il; j = i - 65536; }
    float v = src[j];
    __half h = __float2half_rn(v);
    dh[j] = h;
    dl[j] = __float2half_rn(v - __half2float(h));
}

// ---------------- W_comb = W_op @ W_out (+ b_comb), hi/lo output ----------
__global__ __launch_bounds__(256) void combine_w(
    const float* __restrict__ Wop, const float* __restrict__ Wout,
    const float* __restrict__ bop, const float* __restrict__ bout,
    __half* __restrict__ ch, __half* __restrict__ cl, float* __restrict__ bc)
{
    __shared__ float row[128];
    const int i = blockIdx.x, j = threadIdx.x;
    if (j < 128) row[j] = Wop[i * 128 + j];
    __syncthreads();
    float acc = 0.f;
    for (int k = 0; k < 128; k++) acc += row[k] * Wout[k * 256 + j];
    __half h = __float2half_rn(acc);
    ch[i * 256 + j] = h;
    cl[i * 256 + j] = __float2half_rn(acc - __half2float(h));
    if (i == 0) {
        float b = bout[j];
        for (int k = 0; k < 128; k++) b += bop[k] * Wout[k * 256 + j];
        bc[j] = b;
    }
}

// ====== tensor-core GEMM (mma.sync, fp16 hi/lo, compact smem) ============
constexpr int SAW2 = 72;
constexpr int SBW  = 136;
constexpr int SMEM_A2 = 128 * SAW2 * 2;    // 18432
constexpr int SMEM_B2 = 64 * SBW * 2;      // 17408
constexpr int SM_STAGE2 = SMEM_A2 + SMEM_B2;   // 35840
constexpr int GEMM_SMEM2 = 2 * SM_STAGE2;      // 71680

template<bool ASPLIT, bool OSPLIT>
__global__ __launch_bounds__(256, 2) void tcgemm2(
    const float* __restrict__ A0f, const float* __restrict__ A1f,
    int K0, int sA0, int sA1,
    const __half* __restrict__ Ahi, const __half* __restrict__ Alo,
    const __half* __restrict__ Whi, const __half* __restrict__ Wlo,
    const float* __restrict__ bias,
    float* __restrict__ Cf, __half* __restrict__ Chi, __half* __restrict__ Clo,
    int N, int K)
{
    extern __shared__ char smem[];
    const int tid = threadIdx.x;
    const int wid = tid >> 5, lane = tid & 31;
    const int wm = wid & 3, wn = wid >> 2;
    const long rowBase = (long)blockIdx.y * 128;
    const int  colBase = blockIdx.x * 128;

    float acc[2][8][4];
#pragma unroll
    for (int i = 0; i < 2; i++)
#pragma unroll
        for (int j = 0; j < 8; j++)
#pragma unroll
            for (int e = 0; e < 4; e++) acc[i][j][e] = 0.f;

    const uint32_t sb0 = smem_u32(smem);
    uint32_t aAddr[2], bAddr[4];
#pragma unroll
    for (int mf = 0; mf < 2; mf++)
        aAddr[mf] = sb0 + (uint32_t)(((wm * 32 + mf * 16 + (lane & 15)) * SAW2
                                      + (lane >> 4) * 8) * 2);
#pragma unroll
    for (int ng = 0; ng < 4; ng++)
        bAddr[ng] = sb0 + SMEM_A2 + (uint32_t)(((lane & 15) * SBW
                                      + wn * 64 + ng * 16 + (lane >> 4) * 8) * 2);

    const int nch = K / 32;

    auto loadTiles = [&](int ch, int st) {
        const int kt = ch * 32;
        const uint32_t sbA = sb0 + st * SM_STAGE2;
        const uint32_t sbB = sbA + SMEM_A2;
#pragma unroll
        for (int i = 0; i < 4; i++) {
            int lin = tid + i * 256;
            int row = lin >> 4, u = lin & 15;
            const __half* src = ((row >= 32) ? Wlo : Whi)
                + (long)(kt + (row & 31)) * N + colBase + u * 8;
            cpa16(sbB + (uint32_t)(row * SBW + u * 8) * 2, src);
        }
        if (ASPLIT) {
            const int r = tid >> 1, q = tid & 1;
            const __half* sh = Ahi + (rowBase + r) * (long)K + kt + q * 16;
            const __half* sl = Alo + (rowBase + r) * (long)K + kt + q * 16;
            uint32_t dh = sbA + (uint32_t)(r * SAW2 + q * 16) * 2;
            uint32_t dl = sbA + (uint32_t)(r * SAW2 + 32 + q * 16) * 2;
            cpa16(dh, sh);      cpa16(dh + 16, sh + 8);
            cpa16(dl, sl);      cpa16(dl + 16, sl + 8);
        } else {
            const float* Ap; int sA_, kof;
            if (kt < K0) { Ap = A0f; sA_ = sA0; kof = kt; }
            else         { Ap = A1f; sA_ = sA1; kof = kt - K0; }
            const int r = tid >> 1, q = tid & 1;
            const float4* src = reinterpret_cast<const float4*>(
                Ap + (rowBase + r) * (long)sA_ + kof + q * 16);
            __half* rowp = reinterpret_cast<__half*>(smem + st * SM_STAGE2)
                           + r * SAW2;
#pragma unroll
            for (int j = 0; j < 4; j++) {
                float4 v = src[j];
                int c = q * 16 + j * 4;
                __half hx = __float2half_rn(v.x), hy = __float2half_rn(v.y);
                __half hz = __float2half_rn(v.z), hw = __float2half_rn(v.w);
                __half lx = __float2half_rn(v.x - __half2float(hx));
                __half ly = __float2half_rn(v.y - __half2float(hy));
                __half lz = __float2half_rn(v.z - __half2float(hz));
                __half lw = __float2half_rn(v.w - __half2float(hw));
                __half2 h01 = __halves2half2(hx, hy), h23 = __halves2half2(hz, hw);
                __half2 l01 = __halves2half2(lx, ly), l23 = __halves2half2(lz, lw);
                *reinterpret_cast<uint2*>(rowp + c) =
                    make_uint2(*(uint32_t*)&h01, *(uint32_t*)&h23);
                *reinterpret_cast<uint2*>(rowp + 32 + c) =
                    make_uint2(*(uint32_t*)&l01, *(uint32_t*)&l23);
            }
        }
    };

    loadTiles(0, 0);
    cpa_commit();

    for (int ch = 0; ch < nch; ch++) {
        cpa_wait0();
        __syncthreads();
        if (ch + 1 < nch) { loadTiles(ch + 1, (ch + 1) & 1); cpa_commit(); }

        const uint32_t so = (uint32_t)((ch & 1) * SM_STAGE2);
        const int aof[6] = {0, 16, 32, 48, 0, 16};
        const int bof[6] = {0, 16, 0, 16, 32, 48};
#pragma unroll
        for (int s = 0; s < 6; s++) {
            uint32_t afr[2][4];
            ldsm_x4(afr[0], aAddr[0] + so + aof[s] * 2);
            ldsm_x4(afr[1], aAddr[1] + so + aof[s] * 2);
            uint32_t bfr[4][4];
#pragma unroll
            for (int ng = 0; ng < 4; ng++)
                ldsm_x4_t(bfr[ng], bAddr[ng] + so + bof[s] * SBW * 2);
#pragma unroll
            for (int ng = 0; ng < 4; ng++) {
#pragma unroll
                for (int mf = 0; mf < 2; mf++) {
                    mma16816(acc[mf][ng * 2],     afr[mf], bfr[ng][0], bfr[ng][1]);
                    mma16816(acc[mf][ng * 2 + 1], afr[mf], bfr[ng][2], bfr[ng][3]);
                }
            }
        }
    }

    // ---- epilogue ----
#pragma unroll
    for (int mf = 0; mf < 2; mf++) {
        long row = rowBase + wm * 32 + mf * 16 + (lane >> 2);
#pragma unroll
        for (int nf = 0; nf < 8; nf++) {
            int col = colBase + wn * 64 + nf * 8 + (lane & 3) * 2;
            float bx = bias[col], by = bias[col + 1];
            float v0 = acc[mf][nf][0] + bx, v1 = acc[mf][nf][1] + by;
            float v2 = acc[mf][nf][2] + bx, v3 = acc[mf][nf][3] + by;
            if (OSPLIT) {
                __half h0 = __float2half_rn(v0), h1 = __float2half_rn(v1);
                __half h2 = __float2half_rn(v2), h3 = __float2half_rn(v3);
                __half2 hi0 = __halves2half2(h0, h1), hi1 = __halves2half2(h2, h3);
                __half2 lo0 = __halves2half2(
                    __float2half_rn(v0 - __half2float(h0)),
                    __float2half_rn(v1 - __half2float(h1)));
                __half2 lo1 = __halves2half2(
                    __float2half_rn(v2 - __half2float(h2)),
                    __float2half_rn(v3 - __half2float(h3)));
                *reinterpret_cast<__half2*>(Chi + row * (long)N + col) = hi0;
                *reinterpret_cast<__half2*>(Clo + row * (long)N + col) = lo0;
                *reinterpret_cast<__half2*>(Chi + (row + 8) * (long)N + col) = hi1;
                *reinterpret_cast<__half2*>(Clo + (row + 8) * (long)N + col) = lo1;
            } else {
                *reinterpret_cast<float2*>(Cf + row * (long)N + col) =
                    make_float2(v0, v1);
                *reinterpret_cast<float2*>(Cf + (row + 8) * (long)N + col) =
                    make_float2(v2, v3);
            }
        }
    }
}

// ---------------- depthwise causal conv + SiLU, rolling window ------------
__global__ void conv_silu_kernel(const float* __restrict__ xz,
                                 const float* __restrict__ cw,
                                 const float* __restrict__ cb,
                                 float* __restrict__ xc)
{
    int gid = blockIdx.x * 256 + threadIdx.x;   // 0 .. 1048575
    int d = gid & 255;
    long tb = (long)(gid >> 8) * 16;            // token base
    int l = (int)(tb & (L_ - 1));

    const float w0 = cw[d * 4 + 0], w1 = cw[d * 4 + 1];
    const float w2 = cw[d * 4 + 2], w3 = cw[d * 4 + 3];
    const float cbd = cb[d];

    float x3 = 0.f, x2 = 0.f, x1 = 0.f;
    if (l > 0) {
        x3 = xz[(tb - 3) * 512 + d];
        x2 = xz[(tb - 2) * 512 + d];
        x1 = xz[(tb - 1) * 512 + d];
    }
#pragma unroll
    for (int t = 0; t < 16; t++) {
        float xt = xz[(tb + t) * 512 + d];
        float a = cbd + w0 * x3 + w1 * x2 + w2 * x1 + w3 * xt;
        float s = 1.f / (1.f + __expf(-a));
        xc[(tb + t) * 256 + d] = a * s;
        x3 = x2; x2 = x1; x1 = xt;
    }
}

// ---------------- xc @ W_xproj (K=256, N=40), BM=256, acc 8x5 -------------
__global__ __launch_bounds__(256) void xproj_kernel(
    const float* __restrict__ Ain, const float* __restrict__ W,
    float* __restrict__ outp)
{
    constexpr int BK = 32;
    __shared__ float As[256][36];
    __shared__ float Bs[BK][40];
    const int tid = threadIdx.x;
    const int tx = tid & 7;
    const int ty = tid >> 3;
    const long rowBase = (long)blockIdx.x * 256;

    float acc[8][5];
#pragma unroll
    for (int i = 0; i < 8; i++)
#pragma unroll
        for (int j = 0; j < 5; j++) acc[i][j] = 0.f;

    for (int kt = 0; kt < 256; kt += BK) {
#pragma unroll
        for (int i = 0; i < 8; i++) {
            int lin = tid + i * 256;
            int r   = lin >> 3;
            int k4  = (lin & 7) * 4;
            float4 v = *reinterpret_cast<const float4*>(
                Ain + (rowBase + r) * 256 + kt + k4);
            *reinterpret_cast<float4*>(&As[r][k4]) = v;
        }
#pragma unroll
        for (int i = 0; i < 5; i++) {
            int lin = tid + i * 256;
            int kr = lin / 40, c = lin % 40;
            Bs[kr][c] = W[(kt + kr) * 40 + c];
        }
        __syncthreads();
#pragma unroll
        for (int k = 0; k < BK; k++) {
            float b[5];
#pragma unroll
            for (int j = 0; j < 5; j++) b[j] = Bs[k][tx * 5 + j];
#pragma unroll
            for (int i = 0; i < 8; i++) {
                float a = As[ty + 32 * i][k];
#pragma unroll
                for (int j = 0; j < 5; j++) acc[i][j] += a * b[j];
            }
        }
        __syncthreads();
    }
#pragma unroll
    for (int i = 0; i < 8; i++) {
        long row = rowBase + ty + 32 * i;
#pragma unroll
        for (int j = 0; j < 5; j++) outp[row * 40 + tx * 5 + j] = acc[i][j];
    }
}

// ---------------- scan phase A (dt recomputed in-kernel) ------------------
__global__ __launch_bounds__(256) void scanA_kernel(
    const float* __restrict__ xcg, const float* __restrict__ dbl,
    const float* __restrict__ W_dt, const float* __restrict__ b_dt,
    const float* __restrict__ A_log,
    float* __restrict__ hloc, float* __restrict__ sumdtArr)
{
    const int bid = blockIdx.x;
    const int b = bid / NC, c = bid % NC;
    const long mbase = (long)b * L_ + (long)c * CL;
    const int d = threadIdx.x;

    float Ar[16]; bool fast = true;
#pragma unroll
    for (int s = 0; s < 16; s++) {
        Ar[s] = -__expf(A_log[d * 16 + s]);
        float n = (float)(s + 1);
        fast = fast && (fabsf(Ar[s] + n) < 1e-3f * n);
    }
    float wdt[8];
#pragma unroll
    for (int k = 0; k < 8; k++) wdt[k] = W_dt[k * 256 + d];
    const float bb = b_dt[d];

    __shared__ float sB[CL][16];
    __shared__ float sD[CL][8];
#pragma unroll
    for (int i = 0; i < 4; i++) {
        int lin = threadIdx.x + i * 256;
        sB[lin >> 4][lin & 15] = dbl[(mbase + (lin >> 4)) * 40 + 8 + (lin & 15)];
    }
#pragma unroll
    for (int i = 0; i < 2; i++) {
        int lin = threadIdx.x + i * 256;
        sD[lin >> 3][lin & 7] = dbl[(mbase + (lin >> 3)) * 40 + (lin & 7)];
    }
    __syncthreads();

    float h[16];
#pragma unroll
    for (int s = 0; s < 16; s++) h[s] = 0.f;
    float sumdt = 0.f;

    for (int t = 0; t < CL; t++) {
        long m = mbase + t;
        float pre = bb;
#pragma unroll
        for (int k = 0; k < 8; k++) pre += sD[t][k] * wdt[k];
        float e = __expf(pre);
        float dtv = (pre > 15.f) ? pre : __logf(1.f + e);
        float p = __fdividef(1.f, 1.f + e);       // exp(-softplus(pre))
        float xv = xcg[m * 256 + d];
        sumdt += dtv;
        float cc = dtv * xv;
        float pw[16];
        if (fast) {
            float p2 = p * p, p4 = p2 * p2, p8 = p4 * p4;
            pw[0] = p;        pw[1] = p2;       pw[2] = p2 * p;    pw[3] = p4;
            pw[4] = p4 * p;   pw[5] = p4 * p2;  pw[6] = p4 * pw[2];
            pw[7] = p8;       pw[8] = p8 * p;   pw[9] = p8 * p2;   pw[10] = p8 * pw[2];
            pw[11] = p8 * p4; pw[12] = p8 * pw[4]; pw[13] = p8 * pw[5];
            pw[14] = p8 * pw[6]; pw[15] = p8 * p8;
        } else {
#pragma unroll
            for (int s = 0; s < 16; s++) pw[s] = __expf(dtv * Ar[s]);
        }
#pragma unroll
        for (int s = 0; s < 16; s++) h[s] = pw[s] * h[s] + cc * sB[t][s];
    }

    long o = ((long)bid * 256 + d) * 16;
#pragma unroll
    for (int s = 0; s < 16; s += 4)
        *reinterpret_cast<float4*>(hloc + o + s) =
            make_float4(h[s], h[s + 1], h[s + 2], h[s + 3]);
    sumdtArr[(long)bid * 256 + d] = sumdt;
}

// ---------------- scan phase B ------------------------------------------
__global__ void scanB_kernel(const float* __restrict__ hloc,
                             const float* __restrict__ sumdtArr,
                             const float* __restrict__ A_log,
                             float* __restrict__ hin)
{
    int gid = blockIdx.x * 256 + threadIdx.x;
    int b = gid >> 12;
    int r = gid & 4095;
    int d = r >> 4, s = r & 15;
    float As_ = -__expf(A_log[d * 16 + s]);
    float h = 0.f;
    for (int c = 0; c < NC; c++) {
        long idx = ((long)(b * NC + c) * 256 + d);
        hin[idx * 16 + s] = h;
        float pw = __expf(As_ * sumdtArr[idx]);
        h = pw * h + hloc[idx * 16 + s];
    }
}

// ---------------- scan phase C: replay + gate, dt recomputed --------------
__global__ __launch_bounds__(256) void scanC_kernel(
    const float* __restrict__ xcg, const float* __restrict__ xz,
    const float* __restrict__ dbl,
    const float* __restrict__ W_dt, const float* __restrict__ b_dt,
    const float* __restrict__ A_log, const float* __restrict__ Dp,
    const float* __restrict__ hin,
    __half* __restrict__ yhi, __half* __restrict__ ylo)
{
    const int bid = blockIdx.x;
    const int b = bid / NC, c = bid % NC;
    const long mbase = (long)b * L_ + (long)c * CL;
    const int d = threadIdx.x;

    float Ar[16]; bool fast = true;
#pragma unroll
    for (int s = 0; s < 16; s++) {
        Ar[s] = -__expf(A_log[d * 16 + s]);
        float n = (float)(s + 1);
        fast = fast && (fabsf(Ar[s] + n) < 1e-3f * n);
    }
    float wdt[8];
#pragma unroll
    for (int k = 0; k < 8; k++) wdt[k] = W_dt[k * 256 + d];
    const float bb = b_dt[d];

    __shared__ float sB[CL][16];
    __shared__ float sC[CL][16];
    __shared__ float sD[CL][8];
#pragma unroll
    for (int i = 0; i < 4; i++) {
        int lin = threadIdx.x + i * 256;
        long mm = mbase + (lin >> 4);
        sB[lin >> 4][lin & 15] = dbl[mm * 40 + 8  + (lin & 15)];
        sC[lin >> 4][lin & 15] = dbl[mm * 40 + 24 + (lin & 15)];
    }
#pragma unroll
    for (int i = 0; i < 2; i++) {
        int lin = threadIdx.x + i * 256;
        sD[lin >> 3][lin & 7] = dbl[(mbase + (lin >> 3)) * 40 + (lin & 7)];
    }
    __syncthreads();

    float h[16];
    long o = ((long)bid * 256 + d) * 16;
#pragma unroll
    for (int s = 0; s < 16; s += 4) {
        float4 v = *reinterpret_cast<const float4*>(hin + o + s);
        h[s] = v.x; h[s + 1] = v.y; h[s + 2] = v.z; h[s + 3] = v.w;
    }
    const float Dd = Dp[d];

    for (int t = 0; t < CL; t++) {
        long m = mbase + t;
        float pre = bb;
#pragma unroll
        for (int k = 0; k < 8; k++) pre += sD[t][k] * wdt[k];
        float e = __expf(pre);
        float dtv = (pre > 15.f) ? pre : __logf(1.f + e);
        float p = __fdividef(1.f, 1.f + e);
        float xv = xcg[m * 256 + d];
        float cc = dtv * xv;
        float pw[16];
        if (fast) {
            float p2 = p * p, p4 = p2 * p2, p8 = p4 * p4;
            pw[0] = p;        pw[1] = p2;       pw[2] = p2 * p;    pw[3] = p4;
            pw[4] = p4 * p;   pw[5] = p4 * p2;  pw[6] = p4 * pw[2];
            pw[7] = p8;       pw[8] = p8 * p;   pw[9] = p8 * p2;   pw[10] = p8 * pw[2];
            pw[11] = p8 * p4; pw[12] = p8 * pw[4]; pw[13] = p8 * pw[5];
            pw[14] = p8 * pw[6]; pw[15] = p8 * p8;
        } else {
#pragma unroll
            for (int s = 0; s < 16; s++) pw[s] = __expf(dtv * Ar[s]);
        }
        float y = 0.f;
#pragma unroll
        for (int s = 0; s < 16; s++) {
            h[s] = pw[s] * h[s] + cc * sB[t][s];
            y += h[s] * sC[t][s];
        }
        float zv = xz[m * 512 + 256 + d];
        float sg = 1.f / (1.f + __expf(-zv));
        float v = (y + xv * Dd) * (zv * sg);
        __half hh = __float2half_rn(v);
        yhi[m * 256 + d] = hh;
        ylo[m * 256 + d] = __float2half_rn(v - __half2float(hh));
    }
}

// ---------------- launcher (stateless, call-invariant) --------------------
extern "C" void kernel_launch(void* const* d_in, const int* in_sizes, int n_in,
                              void* d_out, int out_size)
{
    const float* x      = (const float*)d_in[0];
    const float* qk     = (const float*)d_in[1];
    const float* W_mix  = (const float*)d_in[2];
    const float* b_mix  = (const float*)d_in[3];
    const float* W_in   = (const float*)d_in[4];
    const float* b_in   = (const float*)d_in[5];
    const float* conv_w = (const float*)d_in[6];
    const float* conv_b = (const float*)d_in[7];
    const float* W_xproj= (const float*)d_in[8];
    const float* W_dt   = (const float*)d_in[9];
    const float* b_dt   = (const float*)d_in[10];
    const float* A_log  = (const float*)d_in[11];
    const float* D_param= (const float*)d_in[12];
    const float* W_op   = (const float*)d_in[13];
    const float* b_op   = (const float*)d_in[14];
    const float* W_out  = (const float*)d_in[15];
    const float* b_out  = (const float*)d_in[16];
    float* out = (float*)d_out;

    float  *pxz, *pxc, *pdbl, *phloc, *phin, *psum, *pbcomb;
    __half *phhi, *phlo, *pyhi, *pylo;
    __half *pwmixh, *pwmixl, *pwinh, *pwinl, *pwch, *pwcl;
    cudaGetSymbolAddress((void**)&pxz,   g_xz);
    cudaGetSymbolAddress((void**)&pxc,   g_xc);
    cudaGetSymbolAddress((void**)&pdbl,  g_dbl);
    cudaGetSymbolAddress((void**)&phloc, g_hloc);
    cudaGetSymbolAddress((void**)&phin,  g_hin);
    cudaGetSymbolAddress((void**)&psum,  g_sumdt);
    cudaGetSymbolAddress((void**)&phhi,  g_h_hi);
    cudaGetSymbolAddress((void**)&phlo,  g_h_lo);
    cudaGetSymbolAddress((void**)&pyhi,  g_yf_hi);
    cudaGetSymbolAddress((void**)&pylo,  g_yf_lo);
    cudaGetSymbolAddress((void**)&pwmixh, g_wmix_hi);
    cudaGetSymbolAddress((void**)&pwmixl, g_wmix_lo);
    cudaGetSymbolAddress((void**)&pwinh,  g_win_hi);
    cudaGetSymbolAddress((void**)&pwinl,  g_win_lo);
    cudaGetSymbolAddress((void**)&pwch,   g_wcomb_hi);
    cudaGetSymbolAddress((void**)&pwcl,   g_wcomb_lo);
    cudaGetSymbolAddress((void**)&pbcomb, g_bcomb);
    cudaFuncSetAttribute(tcgemm2<false, true>,
        cudaFuncAttributeMaxDynamicSharedMemorySize, GEMM_SMEM2);
    cudaFuncSetAttribute(tcgemm2<true, false>,
        cudaFuncAttributeMaxDynamicSharedMemorySize, GEMM_SMEM2);
    cudaFuncSetAttribute(tcgemm2<true, true>,
        cudaFuncAttributeMaxDynamicSharedMemorySize, GEMM_SMEM2);

    dim3 blk(256);
    // weight prep: split Wmix/Win; combine W_op@W_out -> hi/lo + b_comb
    split_all<<<512, 256>>>(W_mix, W_in, pwmixh, pwmixl, pwinh, pwinl);
    combine_w<<<256, 256>>>(W_op, W_out, b_op, b_out, pwch, pwcl, pbcomb);

    // h = concat(x,qk) @ W_mix + b_mix  -> fp16 hi/lo   [65536,128], K=512
    tcgemm2<false, true><<<dim3(1, 512), blk, GEMM_SMEM2>>>(
        x, qk, 256, 256, 256, nullptr, nullptr,
        pwmixh, pwmixl, b_mix, nullptr, phhi, phlo, 128, 512);
    // xz = h @ W_in + b_in  -> fp32                      [65536,512], K=128
    tcgemm2<true, false><<<dim3(4, 512), blk, GEMM_SMEM2>>>(
        nullptr, nullptr, 0, 0, 0, phhi, phlo,
        pwinh, pwinl, b_in, pxz, nullptr, nullptr, 512, 128);
    // xc = silu(causal_conv(xz[:, :256])) — rolling window
    conv_silu_kernel<<<4096, 256>>>(pxz, conv_w, conv_b, pxc);
    // dbl = xc @ W_xproj                                  [65536,40]
    xproj_kernel<<<256, 256>>>(pxc, W_xproj, pdbl);
    // chunked selective scan (dt recomputed in-kernel from dbl)
    scanA_kernel<<<B_ * NC, 256>>>(pxc, pdbl, W_dt, b_dt, A_log, phloc, psum);
    scanB_kernel<<<256, 256>>>(phloc, psum, A_log, phin);
    scanC_kernel<<<B_ * NC, 256>>>(pxc, pxz, pdbl, W_dt, b_dt, A_log, D_param,
                                   phin, pyhi, pylo);
    // out = yf @ (W_op@W_out) + b_comb  -> fp32           [65536,256], K=256
    tcgemm2<true, false><<<dim3(2, 512), blk, GEMM_SMEM2>>>(
        nullptr, nullptr, 0, 0, 0, pyhi, pylo,
        pwch, pwcl, pbcomb, out, nullptr, nullptr, 256, 256);
}